// round 13
// baseline (speedup 1.0000x reference)
#include <cuda_runtime.h>
#include <cuda_bf16.h>
#include <cstdint>
#include <cstddef>

// Problem dims
#define T_STEPS 512
#define BATCH   256
#define DIM     512
#define HID     256
#define FOURH   1024
#define NACT    32
#define OUTC    33
#define M_ROWS  (T_STEPS * BATCH)   // 131072

// Global scratch
__device__ float g_xproj[(size_t)M_ROWS * FOURH];
__device__ __nv_bfloat16 g_ahi[(size_t)M_ROWS * DIM];
__device__ __nv_bfloat16 g_alo[(size_t)M_ROWS * DIM];
__device__ __nv_bfloat16 g_whi[(size_t)DIM * FOURH];
__device__ __nv_bfloat16 g_wlo[(size_t)DIM * FOURH];

// ===========================================================================
// Shared helpers
// ===========================================================================
__device__ __forceinline__ uint32_t smem_u32(const void* p) {
    uint32_t a;
    asm("{ .reg .u64 t; cvta.to.shared.u64 t, %1; cvt.u32.u64 %0, t; }"
        : "=r"(a) : "l"(p));
    return a;
}
__device__ __forceinline__ void ldsm_x4(uint32_t* r, uint32_t addr) {
    asm volatile("ldmatrix.sync.aligned.m8n8.x4.shared.b16 {%0,%1,%2,%3}, [%4];"
        : "=r"(r[0]), "=r"(r[1]), "=r"(r[2]), "=r"(r[3]) : "r"(addr));
}
__device__ __forceinline__ void ldsm_x4_t(uint32_t* r, uint32_t addr) {
    asm volatile("ldmatrix.sync.aligned.m8n8.x4.trans.shared.b16 {%0,%1,%2,%3}, [%4];"
        : "=r"(r[0]), "=r"(r[1]), "=r"(r[2]), "=r"(r[3]) : "r"(addr));
}
__device__ __forceinline__ void ldsm_x2_t(uint32_t* r, uint32_t addr) {
    asm volatile("ldmatrix.sync.aligned.m8n8.x2.trans.shared.b16 {%0,%1}, [%2];"
        : "=r"(r[0]), "=r"(r[1]) : "r"(addr));
}
__device__ __forceinline__ void mma_bf16(float* c, const uint32_t* a,
                                         uint32_t b0, uint32_t b1) {
    asm volatile(
        "mma.sync.aligned.m16n8k16.row.col.f32.bf16.bf16.f32 "
        "{%0,%1,%2,%3}, {%4,%5,%6,%7}, {%8,%9}, {%0,%1,%2,%3};"
        : "+f"(c[0]), "+f"(c[1]), "+f"(c[2]), "+f"(c[3])
        : "r"(a[0]), "r"(a[1]), "r"(a[2]), "r"(a[3]), "r"(b0), "r"(b1));
}
__device__ __forceinline__ uint32_t pack2(__nv_bfloat16 a, __nv_bfloat16 b) {
    union { __nv_bfloat162 v; uint32_t u; } c;
    c.v = __nv_bfloat162(a, b);
    return c.u;
}
__device__ __forceinline__ void split_store4(float4 v,
                                             __nv_bfloat16* hip,
                                             __nv_bfloat16* lop) {
    __nv_bfloat16 h0 = __float2bfloat16_rn(v.x);
    __nv_bfloat16 h1 = __float2bfloat16_rn(v.y);
    __nv_bfloat16 h2 = __float2bfloat16_rn(v.z);
    __nv_bfloat16 h3 = __float2bfloat16_rn(v.w);
    __nv_bfloat16 l0 = __float2bfloat16_rn(v.x - __bfloat162float(h0));
    __nv_bfloat16 l1 = __float2bfloat16_rn(v.y - __bfloat162float(h1));
    __nv_bfloat16 l2 = __float2bfloat16_rn(v.z - __bfloat162float(h2));
    __nv_bfloat16 l3 = __float2bfloat16_rn(v.w - __bfloat162float(h3));
    ((uint32_t*)hip)[0] = pack2(h0, h1);
    ((uint32_t*)hip)[1] = pack2(h2, h3);
    ((uint32_t*)lop)[0] = pack2(l0, l1);
    ((uint32_t*)lop)[1] = pack2(l2, l3);
}
__device__ __forceinline__ void cp16(uint32_t dst, const void* src) {
    asm volatile("cp.async.cg.shared.global [%0], [%1], 16;"
        :: "r"(dst), "l"(src) : "memory");
}
#define CP_COMMIT() asm volatile("cp.async.commit_group;" ::: "memory")
#define CP_WAIT1()  asm volatile("cp.async.wait_group 1;" ::: "memory")

// ---- MUFU-free activations ----
__device__ __forceinline__ float fast_exp(float x) {
    const float L2E = 1.4426950408889634f;
    float t  = fmaf(x, L2E, 12582912.0f);
    int   n  = __float_as_int(t) - 0x4B400000;
    float nf = t - 12582912.0f;
    float r  = fmaf(nf, -0.693359375f, x);
    r = fmaf(nf, 2.12194440e-4f, r);
    float p = 1.9841270e-4f;
    p = fmaf(p, r, 1.3888889e-3f);
    p = fmaf(p, r, 8.3333333e-3f);
    p = fmaf(p, r, 4.1666667e-2f);
    p = fmaf(p, r, 1.6666667e-1f);
    p = fmaf(p, r, 0.5f);
    p = fmaf(p, r, 1.0f);
    p = fmaf(p, r, 1.0f);
    return __int_as_float(__float_as_int(p) + (n << 23));
}
__device__ __forceinline__ float fast_rcp(float d) {
    float r = __int_as_float(0x7EF127EAu - __float_as_int(d));
    r = r * fmaf(-d, r, 2.0f);
    r = r * fmaf(-d, r, 2.0f);
    return r;
}
__device__ __forceinline__ float fsig(float x) {
    x = fminf(fmaxf(x, -30.0f), 30.0f);
    float e = fast_exp(-x);
    return fast_rcp(1.0f + e);
}
__device__ __forceinline__ float ftanh(float x) {
    return fmaf(2.0f, fsig(2.0f * x), -1.0f);
}

// ===========================================================================
// Kernel 0: split inputs + Wx into global bf16 hi/lo (memory-bound pre-pass)
// ===========================================================================
__global__ __launch_bounds__(256) void split_kernel(
    const float* __restrict__ A, const float* __restrict__ W)
{
    const size_t A4 = (size_t)M_ROWS * DIM / 4;
    const size_t W4 = (size_t)DIM * FOURH / 4;
    size_t stride = (size_t)gridDim.x * blockDim.x;
    for (size_t i = (size_t)blockIdx.x * blockDim.x + threadIdx.x;
         i < A4 + W4; i += stride) {
        float4 v;
        __nv_bfloat16 *hp, *lp;
        if (i < A4) {
            v = ((const float4*)A)[i];
            hp = g_ahi + i * 4;
            lp = g_alo + i * 4;
        } else {
            size_t j = i - A4;
            v = ((const float4*)W)[j];
            hp = g_whi + j * 4;
            lp = g_wlo + j * 4;
        }
        split_store4(v, hp, lp);
    }
}

// ===========================================================================
// Kernel 1: x_proj GEMM — pre-split bf16 operands, cp.async 3-stage pipeline.
// Block tile 128x128x32, 256 threads, 8 warps (4M x 2N), warp tile 32x64.
// NOW 2 CTAs/SM (launch_bounds minBlocks=2): 4 warps/SMSP for latency cover.
// ===========================================================================
#define X2_A_BYTES (128 * 80)
#define X2_W_BYTES (32 * 272)
#define X2_STAGE   (2 * X2_A_BYTES + 2 * X2_W_BYTES)   // 37888
#define X2_SMEM    (3 * X2_STAGE)                       // 113664

__global__ __launch_bounds__(256, 2) void xproj_mma_kernel(
    const float* __restrict__ bias)
{
    extern __shared__ char xsm2[];
    const uint32_t smb = smem_u32(xsm2);

    const int tid   = threadIdx.x;
    const int lane  = tid & 31;
    const int wid   = tid >> 5;
    const int warpM = wid & 3;
    const int warpN = wid >> 2;
    const int bM    = blockIdx.y;
    const int bN    = blockIdx.x;

    const size_t aRowBase = (size_t)bM * 128;
    const size_t wColBase = (size_t)bN * 128;

    float acc[2][8][4];
    #pragma unroll
    for (int mt = 0; mt < 2; mt++)
        #pragma unroll
        for (int j = 0; j < 8; j++)
            #pragma unroll
            for (int q = 0; q < 4; q++) acc[mt][j][q] = 0.f;

    const int a_row_l = (lane & 15);
    const int a_koff  = ((lane >> 4) << 3);
    const int b_krow  = (lane & 7) + ((lane >> 3) & 1) * 8;
    const int b_ncol  = ((lane >> 4) & 1) * 8;

    const int ar0 = tid >> 2, ac0 = tid & 3;
    const int kr0 = tid >> 4, c160 = tid & 15;

    auto issue = [&](int st, int k0) {
        uint32_t base = smb + st * X2_STAGE;
        #pragma unroll
        for (int i = 0; i < 2; i++) {
            int ar = (i == 0) ? ar0 : (ar0 + 64);
            int ac = ac0;
            size_t asrc = (aRowBase + ar) * DIM + k0 + ac * 8;
            cp16(base + ar * 80 + ac * 16, g_ahi + asrc);
            cp16(base + X2_A_BYTES + ar * 80 + ac * 16, g_alo + asrc);
            int kr = (i == 0) ? kr0 : (kr0 + 16);
            int c16 = c160;
            size_t wsrc = (size_t)(k0 + kr) * FOURH + wColBase + c16 * 8;
            cp16(base + 2 * X2_A_BYTES + kr * 272 + c16 * 16, g_whi + wsrc);
            cp16(base + 2 * X2_A_BYTES + X2_W_BYTES + kr * 272 + c16 * 16,
                 g_wlo + wsrc);
        }
    };

    issue(0, 0);  CP_COMMIT();
    issue(1, 32); CP_COMMIT();

    const int NSTAGE = DIM / 32;   // 16

    for (int s = 0; s < NSTAGE; s++) {
        CP_WAIT1();
        __syncthreads();

        if (s + 2 < NSTAGE) {
            issue((s + 2) % 3, (s + 2) * 32);
            CP_COMMIT();
        } else {
            CP_COMMIT();
        }

        uint32_t sAhi = smb + (s % 3) * X2_STAGE;
        uint32_t sAlo = sAhi + X2_A_BYTES;
        uint32_t sBhi = sAhi + 2 * X2_A_BYTES;
        uint32_t sBlo = sBhi + X2_W_BYTES;

        #pragma unroll
        for (int ks = 0; ks < 2; ks++) {
            const int kk0 = ks * 16;
            uint32_t aHi[2][4], aLo[2][4];
            #pragma unroll
            for (int mt = 0; mt < 2; mt++) {
                uint32_t off =
                    (uint32_t)((warpM * 32 + mt * 16 + a_row_l) * 40 + kk0 + a_koff) * 2;
                ldsm_x4(aHi[mt], sAhi + off);
                ldsm_x4(aLo[mt], sAlo + off);
            }
            uint32_t bHi[4][4], bLo[4][4];
            #pragma unroll
            for (int nt = 0; nt < 4; nt++) {
                uint32_t off =
                    (uint32_t)((kk0 + b_krow) * 136 + warpN * 64 + nt * 16 + b_ncol) * 2;
                ldsm_x4_t(bHi[nt], sBhi + off);
                ldsm_x4_t(bLo[nt], sBlo + off);
            }
            #pragma unroll
            for (int mt = 0; mt < 2; mt++) {
                #pragma unroll
                for (int j = 0; j < 8; j++) {
                    uint32_t bh0 = bHi[j >> 1][(j & 1) * 2];
                    uint32_t bh1 = bHi[j >> 1][(j & 1) * 2 + 1];
                    uint32_t bl0 = bLo[j >> 1][(j & 1) * 2];
                    uint32_t bl1 = bLo[j >> 1][(j & 1) * 2 + 1];
                    mma_bf16(acc[mt][j], aHi[mt], bh0, bh1);
                    mma_bf16(acc[mt][j], aHi[mt], bl0, bl1);
                    mma_bf16(acc[mt][j], aLo[mt], bh0, bh1);
                }
            }
        }
    }

    const int g  = lane >> 2;
    const int t2 = (lane & 3) * 2;
    #pragma unroll
    for (int mt = 0; mt < 2; mt++) {
        size_t row = aRowBase + warpM * 32 + mt * 16 + g;
        #pragma unroll
        for (int j = 0; j < 8; j++) {
            int col = (int)wColBase + warpN * 64 + j * 8 + t2;
            float b0 = bias[col], b1 = bias[col + 1];
            float2 o0 = make_float2(acc[mt][j][0] + b0, acc[mt][j][1] + b1);
            float2 o1 = make_float2(acc[mt][j][2] + b0, acc[mt][j][3] + b1);
            *(float2*)&g_xproj[row * FOURH + col] = o0;
            *(float2*)&g_xproj[(row + 8) * FOURH + col] = o1;
        }
    }
}

// ===========================================================================
// Kernel 2: recurrent kernel — UNCHANGED from R10 (bulk DSMEM + complete_tx).
// ===========================================================================
#define CLUSTER 8
#define NB      16
#define LC      128
#define RTHREADS 512

#define WSTRIDE 136
#define ZSTRIDE 140

#define HROW     80
#define LO_OFF   1280
#define RANK_BLK 2560
#define HBUF     (CLUSTER * RANK_BLK)

#define SMB_WHHI 0
#define SMB_WHLO (SMB_WHHI + 256 * WSTRIDE * 2)
#define SMB_HB   (SMB_WHLO + 256 * WSTRIDE * 2)
#define SMB_Z0   (SMB_HB + 2 * HBUF)
#define SMB_Z1   (SMB_Z0 + NB * ZSTRIDE * 4)
#define SMB_C    (SMB_Z1 + NB * ZSTRIDE * 4)
#define SMB_WO   (SMB_C + NB * 32 * 4)
#define SMB_BO   (SMB_WO + 5 * 256 * 4)
#define SMB_MBAR (SMB_BO + 32)
#define SMB_EP   (SMB_MBAR + 16)
#define RSMEM_BYTES (SMB_EP + T_STEPS * NB)

__device__ __forceinline__ void mbar_wait_cluster(uint32_t mbar, uint32_t parity) {
    uint32_t done;
    asm volatile(
        "{ .reg .pred p;\n"
        " mbarrier.try_wait.parity.acquire.cluster.shared::cta.b64 p, [%1], %2;\n"
        " selp.b32 %0, 1, 0, p; }"
        : "=r"(done) : "r"(mbar), "r"(parity) : "memory");
    while (!done) {
        asm volatile(
            "{ .reg .pred p;\n"
            " mbarrier.try_wait.parity.acquire.cluster.shared::cta.b64 p, [%1], %2, 0x989680;\n"
            " selp.b32 %0, 1, 0, p; }"
            : "=r"(done) : "r"(mbar), "r"(parity) : "memory");
    }
}

__device__ __forceinline__ void do_head(
    const char* hb,
    const float* Wo_s, const float* bo_s,
    float* out, int tt, int b0, int rank, int wid, int lane)
{
    float sacc[4];
    #pragma unroll
    for (int q = 0; q < 4; q++) {
        const float* wcol = &Wo_s[q * 256];
        float s = 0.f;
        #pragma unroll
        for (int uu = 0; uu < 8; uu++) {
            const char* blk = hb + uu * RANK_BLK + wid * HROW + lane * 2;
            float hv = __bfloat162float(*(const __nv_bfloat16*)blk)
                     + __bfloat162float(*(const __nv_bfloat16*)(blk + LO_OFF));
            s = fmaf(hv, wcol[lane + 32 * uu], s);
        }
        sacc[q] = s;
    }
    float sv = 0.f;
    if (rank == 0) {
        const float* wcol = &Wo_s[4 * 256];
        #pragma unroll
        for (int uu = 0; uu < 8; uu++) {
            const char* blk = hb + uu * RANK_BLK + wid * HROW + lane * 2;
            float hv = __bfloat162float(*(const __nv_bfloat16*)blk)
                     + __bfloat162float(*(const __nv_bfloat16*)(blk + LO_OFF));
            sv = fmaf(hv, wcol[lane + 32 * uu], sv);
        }
    }
    #pragma unroll
    for (int q = 0; q < 4; q++) {
        float s = sacc[q];
        #pragma unroll
        for (int off = 16; off; off >>= 1)
            s += __shfl_xor_sync(0xFFFFFFFFu, s, off);
        sacc[q] = s;
    }
    #pragma unroll
    for (int off = 16; off; off >>= 1)
        sv += __shfl_xor_sync(0xFFFFFFFFu, sv, off);
    if (lane == 0) {
        size_t obase = ((size_t)tt * BATCH + b0 + wid) * OUTC;
        #pragma unroll
        for (int q = 0; q < 4; q++)
            out[obase + rank + 8 * q] = sacc[q] + bo_s[q];
        if (rank == 0)
            out[obase + 32] = sv + bo_s[4];
    }
}

__global__ void __cluster_dims__(CLUSTER, 1, 1) __launch_bounds__(RTHREADS, 1)
lstm_rec_kernel(const int*   __restrict__ epi,
                const float* __restrict__ carry_c,
                const float* __restrict__ carry_h,
                const float* __restrict__ Wh,
                const float* __restrict__ Wa,
                const float* __restrict__ ba,
                const float* __restrict__ Wv,
                const float* __restrict__ bv,
                float*       __restrict__ out)
{
    extern __shared__ char smraw[];
    __nv_bfloat16* WhHi = (__nv_bfloat16*)(smraw + SMB_WHHI);
    __nv_bfloat16* WhLo = (__nv_bfloat16*)(smraw + SMB_WHLO);
    float* z0_s = (float*)(smraw + SMB_Z0);
    float* z1_s = (float*)(smraw + SMB_Z1);
    float* c_s  = (float*)(smraw + SMB_C);
    float* Wo_s = (float*)(smraw + SMB_WO);
    float* bo_s = (float*)(smraw + SMB_BO);
    unsigned char* ep_s = (unsigned char*)(smraw + SMB_EP);

    const int tid  = threadIdx.x;
    const int lane = tid & 31;
    const int wid  = tid >> 5;
    const int wn   = wid & 7;
    const int kh   = wid >> 3;
    uint32_t rank;
    asm("mov.u32 %0, %%cluster_ctarank;" : "=r"(rank));
    const int cl = blockIdx.x / CLUSTER;
    const int b0 = cl * NB;
    const uint32_t smbase = smem_u32(smraw);

    if (tid == 0) {
        asm volatile("mbarrier.init.shared.b64 [%0], %1;"
            :: "r"(smbase + SMB_MBAR), "r"(1u) : "memory");
        asm volatile("mbarrier.init.shared.b64 [%0], %1;"
            :: "r"(smbase + SMB_MBAR + 8), "r"(1u) : "memory");
    }

    for (int idx = tid; idx < 256 * LC; idx += RTHREADS) {
        int k = idx >> 7;
        int c = idx & 127;
        int gcol = ((c >> 5) << 8) + ((int)rank << 5) + (c & 31);
        float w = Wh[k * FOURH + gcol];
        __nv_bfloat16 hi = __float2bfloat16_rn(w);
        __nv_bfloat16 lo = __float2bfloat16_rn(w - __bfloat162float(hi));
        WhHi[k * WSTRIDE + c] = hi;
        WhLo[k * WSTRIDE + c] = lo;
    }
    for (int idx = tid; idx < 256 * 8; idx += RTHREADS) {
        int k = idx >> 3;
        int c = idx & 7;
        float w = 0.f;
        if (c < 4)                     w = Wa[k * NACT + (int)rank + 8 * c];
        else if (c == 4 && rank == 0)  w = Wv[k];
        __nv_bfloat16 hi = __float2bfloat16_rn(w);
        __nv_bfloat16 lo = __float2bfloat16_rn(w - __bfloat162float(hi));
        WhHi[k * WSTRIDE + 128 + c] = hi;
        WhLo[k * WSTRIDE + 128 + c] = lo;
    }
    for (int idx = tid; idx < NB * HID; idx += RTHREADS) {
        int b = idx >> 8;
        int k = idx & 255;
        float v = carry_h[(size_t)(b0 + b) * HID + k];
        __nv_bfloat16 hi = __float2bfloat16_rn(v);
        __nv_bfloat16 lo = __float2bfloat16_rn(v - __bfloat162float(hi));
        char* blk = smraw + SMB_HB + 1 * HBUF + (k >> 5) * RANK_BLK;
        *(__nv_bfloat16*)(blk + b * HROW + (k & 31) * 2) = hi;
        *(__nv_bfloat16*)(blk + LO_OFF + b * HROW + (k & 31) * 2) = lo;
    }
    for (int idx = tid; idx < NB * 32; idx += RTHREADS) {
        int b = idx >> 5;
        int j = idx & 31;
        c_s[idx] = carry_c[(size_t)(b0 + b) * HID + (int)rank * 32 + j];
    }
    #pragma unroll
    for (int q = 0; q < 5; q++) {
        int col = (int)rank + 8 * q;
        if (col <= 32) {
            for (int k = tid; k < HID; k += RTHREADS)
                Wo_s[q * 256 + k] = (col < 32) ? Wa[k * NACT + col] : Wv[k];
            if (tid == 0) bo_s[q] = (col < 32) ? ba[col] : bv[0];
        }
    }
    for (int idx = tid; idx < T_STEPS * NB; idx += RTHREADS) {
        int t = idx >> 4;
        int b = idx & 15;
        ep_s[idx] = (unsigned char)(epi[t * BATCH + b0 + b] != 0);
    }
    __syncthreads();
    asm volatile("barrier.cluster.arrive.aligned;" ::: "memory");
    asm volatile("barrier.cluster.wait.aligned;"   ::: "memory");

    const int a_row_l = (lane & 15);
    const int a_koff  = ((lane >> 4) << 3);
    const int b_krow  = (lane & 7) + ((lane >> 3) & 1) * 8;
    const int b_ncol  = ((lane >> 4) & 1) * 8;
    const int kbase   = kh * 128;

    const uint32_t sWhHi = smem_u32(WhHi);
    const uint32_t sWhLo = smem_u32(WhLo);
    float* zw_s = kh ? z1_s : z0_s;

    int ph0 = 0, ph1 = 0;

    const int gb = tid >> 5;
    const int gj = tid & 31;

    const int cp_peer = tid + (tid >= (int)rank);

    for (int t = 0; t < T_STEPS; t++) {
        const int p_out = t & 1;
        const int p_in  = p_out ^ 1;
        const uint32_t hinBase  = smbase + SMB_HB + (uint32_t)p_in * HBUF;
        char* houtB = smraw + SMB_HB + p_out * HBUF + (int)rank * RANK_BLK;

        if (tid == 0) {
            uint32_t mb = smbase + SMB_MBAR + (uint32_t)(((t + 1) & 1) * 8);
            asm volatile("mbarrier.arrive.expect_tx.shared.b64 _, [%0], %1;"
                :: "r"(mb), "r"((uint32_t)(7 * RANK_BLK)) : "memory");
        }

        const size_t xbase = (size_t)t * BATCH * FOURH
                           + (size_t)(b0 + gb) * FOURH + (int)rank * 32 + gj;
        float xi = g_xproj[xbase];
        float xf = g_xproj[xbase + 256];
        float xg = g_xproj[xbase + 512];
        float xo = g_xproj[xbase + 768];
        int   ep = ep_s[t * NB + gb];

        if (t > 0) {
            if (t & 1) { mbar_wait_cluster(smbase + SMB_MBAR + 8, ph1); ph1 ^= 1; }
            else       { mbar_wait_cluster(smbase + SMB_MBAR,     ph0); ph0 ^= 1; }
        }

        {
            float acc[2][4][4];
            float accH[2][4];
            #pragma unroll
            for (int t2 = 0; t2 < 2; t2++) {
                #pragma unroll
                for (int kc = 0; kc < 4; kc++)
                    #pragma unroll
                    for (int q = 0; q < 4; q++) acc[t2][kc][q] = 0.f;
                #pragma unroll
                for (int q = 0; q < 4; q++) accH[t2][q] = 0.f;
            }

            #pragma unroll
            for (int ks = 0; ks < 8; ks++) {
                const int kk0 = kbase + ks * 16;
                const int kc  = ks & 3;
                const int blk = kk0 >> 5;
                uint32_t aoff = hinBase + (uint32_t)(blk * RANK_BLK
                               + a_row_l * HROW + ((kk0 & 16) + a_koff) * 2);
                uint32_t aHi[4], aLo[4];
                ldsm_x4(aHi, aoff);
                ldsm_x4(aLo, aoff + LO_OFF);
                uint32_t boff =
                    (uint32_t)((kk0 + b_krow) * WSTRIDE + wn * 16 + b_ncol) * 2;
                uint32_t bHi[4], bLo[4];
                ldsm_x4_t(bHi, sWhHi + boff);
                ldsm_x4_t(bLo, sWhLo + boff);
                #pragma unroll
                for (int t2 = 0; t2 < 2; t2++) {
                    mma_bf16(acc[t2][kc], aHi, bHi[t2 * 2], bHi[t2 * 2 + 1]);
                    mma_bf16(acc[t2][kc], aHi, bLo[t2 * 2], bLo[t2 * 2 + 1]);
                    mma_bf16(acc[t2][kc], aLo, bHi[t2 * 2], bHi[t2 * 2 + 1]);
                }
                if (wn == 0) {
                    uint32_t hoff = (uint32_t)((kk0 + b_krow) * WSTRIDE + 128) * 2;
                    uint32_t hH[2], hL[2];
                    ldsm_x2_t(hH, sWhHi + hoff);
                    ldsm_x2_t(hL, sWhLo + hoff);
                    const int kc2 = ks & 1;
                    mma_bf16(accH[kc2], aHi, hH[0], hH[1]);
                    mma_bf16(accH[kc2], aHi, hL[0], hL[1]);
                    mma_bf16(accH[kc2], aLo, hH[0], hH[1]);
                }
            }
            int r0 = lane >> 2;
            int cb = wn * 16 + 2 * (lane & 3);
            #pragma unroll
            for (int t2 = 0; t2 < 2; t2++) {
                int col = cb + 8 * t2;
                float v0 = (acc[t2][0][0] + acc[t2][1][0]) + (acc[t2][2][0] + acc[t2][3][0]);
                float v1 = (acc[t2][0][1] + acc[t2][1][1]) + (acc[t2][2][1] + acc[t2][3][1]);
                float v2 = (acc[t2][0][2] + acc[t2][1][2]) + (acc[t2][2][2] + acc[t2][3][2]);
                float v3 = (acc[t2][0][3] + acc[t2][1][3]) + (acc[t2][2][3] + acc[t2][3][3]);
                *(float2*)&zw_s[r0 * ZSTRIDE + col] = make_float2(v0, v1);
                *(float2*)&zw_s[(r0 + 8) * ZSTRIDE + col] = make_float2(v2, v3);
            }
            if (wn == 0) {
                int colH = 128 + 2 * (lane & 3);
                float h0 = accH[0][0] + accH[1][0];
                float h1 = accH[0][1] + accH[1][1];
                float h2 = accH[0][2] + accH[1][2];
                float h3 = accH[0][3] + accH[1][3];
                *(float2*)&zw_s[r0 * ZSTRIDE + colH] = make_float2(h0, h1);
                *(float2*)&zw_s[(r0 + 8) * ZSTRIDE + colH] = make_float2(h2, h3);
            }
        }
        __syncthreads();

        if (t > 0) {
            if (tid < 64) {
                int b = tid >> 2, q = tid & 3;
                out[((size_t)(t - 1) * BATCH + b0 + b) * OUTC + (int)rank + 8 * q]
                    = z0_s[b * ZSTRIDE + 128 + q] + z1_s[b * ZSTRIDE + 128 + q] + bo_s[q];
            } else if (rank == 0 && tid < 80) {
                int b = tid - 64;
                out[((size_t)(t - 1) * BATCH + b0 + b) * OUTC + 32]
                    = z0_s[b * ZSTRIDE + 132] + z1_s[b * ZSTRIDE + 132] + bo_s[4];
            }
        }

        {
            float zi = z0_s[gb * ZSTRIDE + gj]      + z1_s[gb * ZSTRIDE + gj];
            float zf = z0_s[gb * ZSTRIDE + 32 + gj] + z1_s[gb * ZSTRIDE + 32 + gj];
            float zg = z0_s[gb * ZSTRIDE + 64 + gj] + z1_s[gb * ZSTRIDE + 64 + gj];
            float zo = z0_s[gb * ZSTRIDE + 96 + gj] + z1_s[gb * ZSTRIDE + 96 + gj];
            float c_old = c_s[gb * 32 + gj];
            if (ep) { zi = 0.f; zf = 0.f; zg = 0.f; zo = 0.f; c_old = 0.f; }
            float iz = zi + xi;
            float fz = zf + xf;
            float gz = zg + xg;
            float oz = zo + xo;
            float nc = fsig(fz) * c_old + fsig(iz) * ftanh(gz);
            float nh = fsig(oz) * ftanh(nc);
            c_s[gb * 32 + gj] = nc;
            __nv_bfloat16 hi = __float2bfloat16_rn(nh);
            __nv_bfloat16 lo = __float2bfloat16_rn(nh - __bfloat162float(hi));
            *(__nv_bfloat16*)(houtB + gb * HROW + gj * 2) = hi;
            *(__nv_bfloat16*)(houtB + LO_OFF + gb * HROW + gj * 2) = lo;
        }
        __syncthreads();

        if (tid < 7) {
            asm volatile("fence.proxy.async.shared::cta;" ::: "memory");
            uint32_t src = smbase + (uint32_t)(SMB_HB + p_out * HBUF
                                               + (int)rank * RANK_BLK);
            uint32_t dst, mb;
            asm("mapa.shared::cluster.u32 %0, %1, %2;"
                : "=r"(dst) : "r"(src), "r"(cp_peer));
            uint32_t mbl = smbase + SMB_MBAR + (uint32_t)(((t + 1) & 1) * 8);
            asm("mapa.shared::cluster.u32 %0, %1, %2;"
                : "=r"(mb) : "r"(mbl), "r"(cp_peer));
            asm volatile(
                "cp.async.bulk.shared::cluster.shared::cta.mbarrier::complete_tx::bytes "
                "[%0], [%1], %2, [%3];"
                :: "r"(dst), "r"(src), "r"((uint32_t)RANK_BLK), "r"(mb) : "memory");
        }
    }

    {
        mbar_wait_cluster(smbase + SMB_MBAR, ph0);
        do_head(smraw + SMB_HB + 1 * HBUF, Wo_s, bo_s, out,
                T_STEPS - 1, b0, (int)rank, wid, lane);
    }

    asm volatile("barrier.cluster.arrive.aligned;" ::: "memory");
    asm volatile("barrier.cluster.wait.aligned;"   ::: "memory");
}

// ---------------------------------------------------------------------------
extern "C" void kernel_launch(void* const* d_in, const int* in_sizes, int n_in,
                              void* d_out, int out_size) {
    const float* inputs  = (const float*)d_in[0];
    const int*   epi     = (const int*)  d_in[1];
    const float* carry_c = (const float*)d_in[2];
    const float* carry_h = (const float*)d_in[3];
    const float* Wx      = (const float*)d_in[4];
    const float* Wh      = (const float*)d_in[5];
    const float* bias    = (const float*)d_in[6];
    const float* Wa      = (const float*)d_in[7];
    const float* ba      = (const float*)d_in[8];
    const float* Wv      = (const float*)d_in[9];
    const float* bv      = (const float*)d_in[10];
    float* out = (float*)d_out;

    cudaFuncSetAttribute(xproj_mma_kernel,
                         cudaFuncAttributeMaxDynamicSharedMemorySize, X2_SMEM);
    cudaFuncSetAttribute(lstm_rec_kernel,
                         cudaFuncAttributeMaxDynamicSharedMemorySize, RSMEM_BYTES);

    split_kernel<<<2048, 256>>>(inputs, Wx);

    dim3 g1(FOURH / 128, M_ROWS / 128);   // (8, 1024)
    xproj_mma_kernel<<<g1, 256, X2_SMEM>>>(bias);

    lstm_rec_kernel<<<(BATCH / NB) * CLUSTER, RTHREADS, RSMEM_BYTES>>>(
        epi, carry_c, carry_h, Wh, Wa, ba, Wv, bv, out);
}

// round 14
// speedup vs baseline: 1.5412x; 1.5412x over previous
#include <cuda_runtime.h>
#include <cuda_bf16.h>
#include <cstdint>
#include <cstddef>

// Problem dims
#define T_STEPS 512
#define BATCH   256
#define DIM     512
#define HID     256
#define FOURH   1024
#define NACT    32
#define OUTC    33
#define M_ROWS  (T_STEPS * BATCH)   // 131072

// Global scratch
__device__ float g_xproj[(size_t)M_ROWS * FOURH];
__device__ __nv_bfloat16 g_ahi[(size_t)M_ROWS * DIM];
__device__ __nv_bfloat16 g_alo[(size_t)M_ROWS * DIM];
__device__ __nv_bfloat16 g_whi[(size_t)DIM * FOURH];
__device__ __nv_bfloat16 g_wlo[(size_t)DIM * FOURH];

// ===========================================================================
// Shared helpers
// ===========================================================================
__device__ __forceinline__ uint32_t smem_u32(const void* p) {
    uint32_t a;
    asm("{ .reg .u64 t; cvta.to.shared.u64 t, %1; cvt.u32.u64 %0, t; }"
        : "=r"(a) : "l"(p));
    return a;
}
__device__ __forceinline__ void ldsm_x4(uint32_t* r, uint32_t addr) {
    asm volatile("ldmatrix.sync.aligned.m8n8.x4.shared.b16 {%0,%1,%2,%3}, [%4];"
        : "=r"(r[0]), "=r"(r[1]), "=r"(r[2]), "=r"(r[3]) : "r"(addr));
}
__device__ __forceinline__ void ldsm_x4_t(uint32_t* r, uint32_t addr) {
    asm volatile("ldmatrix.sync.aligned.m8n8.x4.trans.shared.b16 {%0,%1,%2,%3}, [%4];"
        : "=r"(r[0]), "=r"(r[1]), "=r"(r[2]), "=r"(r[3]) : "r"(addr));
}
__device__ __forceinline__ void ldsm_x2_t(uint32_t* r, uint32_t addr) {
    asm volatile("ldmatrix.sync.aligned.m8n8.x2.trans.shared.b16 {%0,%1}, [%2];"
        : "=r"(r[0]), "=r"(r[1]) : "r"(addr));
}
__device__ __forceinline__ void mma_bf16(float* c, const uint32_t* a,
                                         uint32_t b0, uint32_t b1) {
    asm volatile(
        "mma.sync.aligned.m16n8k16.row.col.f32.bf16.bf16.f32 "
        "{%0,%1,%2,%3}, {%4,%5,%6,%7}, {%8,%9}, {%0,%1,%2,%3};"
        : "+f"(c[0]), "+f"(c[1]), "+f"(c[2]), "+f"(c[3])
        : "r"(a[0]), "r"(a[1]), "r"(a[2]), "r"(a[3]), "r"(b0), "r"(b1));
}
__device__ __forceinline__ uint32_t pack2(__nv_bfloat16 a, __nv_bfloat16 b) {
    union { __nv_bfloat162 v; uint32_t u; } c;
    c.v = __nv_bfloat162(a, b);
    return c.u;
}
__device__ __forceinline__ void split_store4(float4 v,
                                             __nv_bfloat16* hip,
                                             __nv_bfloat16* lop) {
    __nv_bfloat16 h0 = __float2bfloat16_rn(v.x);
    __nv_bfloat16 h1 = __float2bfloat16_rn(v.y);
    __nv_bfloat16 h2 = __float2bfloat16_rn(v.z);
    __nv_bfloat16 h3 = __float2bfloat16_rn(v.w);
    __nv_bfloat16 l0 = __float2bfloat16_rn(v.x - __bfloat162float(h0));
    __nv_bfloat16 l1 = __float2bfloat16_rn(v.y - __bfloat162float(h1));
    __nv_bfloat16 l2 = __float2bfloat16_rn(v.z - __bfloat162float(h2));
    __nv_bfloat16 l3 = __float2bfloat16_rn(v.w - __bfloat162float(h3));
    ((uint32_t*)hip)[0] = pack2(h0, h1);
    ((uint32_t*)hip)[1] = pack2(h2, h3);
    ((uint32_t*)lop)[0] = pack2(l0, l1);
    ((uint32_t*)lop)[1] = pack2(l2, l3);
}
__device__ __forceinline__ void cp16(uint32_t dst, const void* src) {
    asm volatile("cp.async.cg.shared.global [%0], [%1], 16;"
        :: "r"(dst), "l"(src) : "memory");
}
#define CP_COMMIT() asm volatile("cp.async.commit_group;" ::: "memory")
#define CP_WAIT1()  asm volatile("cp.async.wait_group 1;" ::: "memory")

// ---- MUFU-free activations ----
__device__ __forceinline__ float fast_exp(float x) {
    const float L2E = 1.4426950408889634f;
    float t  = fmaf(x, L2E, 12582912.0f);
    int   n  = __float_as_int(t) - 0x4B400000;
    float nf = t - 12582912.0f;
    float r  = fmaf(nf, -0.693359375f, x);
    r = fmaf(nf, 2.12194440e-4f, r);
    float p = 1.9841270e-4f;
    p = fmaf(p, r, 1.3888889e-3f);
    p = fmaf(p, r, 8.3333333e-3f);
    p = fmaf(p, r, 4.1666667e-2f);
    p = fmaf(p, r, 1.6666667e-1f);
    p = fmaf(p, r, 0.5f);
    p = fmaf(p, r, 1.0f);
    p = fmaf(p, r, 1.0f);
    return __int_as_float(__float_as_int(p) + (n << 23));
}
__device__ __forceinline__ float fast_rcp(float d) {
    float r = __int_as_float(0x7EF127EAu - __float_as_int(d));
    r = r * fmaf(-d, r, 2.0f);
    r = r * fmaf(-d, r, 2.0f);
    return r;
}
__device__ __forceinline__ float fsig(float x) {
    x = fminf(fmaxf(x, -30.0f), 30.0f);
    float e = fast_exp(-x);
    return fast_rcp(1.0f + e);
}
__device__ __forceinline__ float ftanh(float x) {
    return fmaf(2.0f, fsig(2.0f * x), -1.0f);
}

// ===========================================================================
// Kernel 0: split inputs + Wx into global bf16 hi/lo (memory-bound pre-pass)
// ===========================================================================
__global__ __launch_bounds__(256) void split_kernel(
    const float* __restrict__ A, const float* __restrict__ W)
{
    const size_t A4 = (size_t)M_ROWS * DIM / 4;
    const size_t W4 = (size_t)DIM * FOURH / 4;
    size_t stride = (size_t)gridDim.x * blockDim.x;
    for (size_t i = (size_t)blockIdx.x * blockDim.x + threadIdx.x;
         i < A4 + W4; i += stride) {
        float4 v;
        __nv_bfloat16 *hp, *lp;
        if (i < A4) {
            v = ((const float4*)A)[i];
            hp = g_ahi + i * 4;
            lp = g_alo + i * 4;
        } else {
            size_t j = i - A4;
            v = ((const float4*)W)[j];
            hp = g_whi + j * 4;
            lp = g_wlo + j * 4;
        }
        split_store4(v, hp, lp);
    }
}

// ===========================================================================
// Kernel 1: x_proj GEMM — pre-split bf16, cp.async 3-stage pipeline.
// 2 CTAs/SM; inner loop holds only HALF the B fragments at a time so the
// live register set (~111) fits the 128-reg cap without spilling.
// ===========================================================================
#define X2_A_BYTES (128 * 80)
#define X2_W_BYTES (32 * 272)
#define X2_STAGE   (2 * X2_A_BYTES + 2 * X2_W_BYTES)   // 37888
#define X2_SMEM    (3 * X2_STAGE)                       // 113664

__global__ __launch_bounds__(256, 2) void xproj_mma_kernel(
    const float* __restrict__ bias)
{
    extern __shared__ char xsm2[];
    const uint32_t smb = smem_u32(xsm2);

    const int tid   = threadIdx.x;
    const int lane  = tid & 31;
    const int wid   = tid >> 5;
    const int warpM = wid & 3;
    const int warpN = wid >> 2;
    const int bM    = blockIdx.y;
    const int bN    = blockIdx.x;

    const size_t aRowBase = (size_t)bM * 128;
    const size_t wColBase = (size_t)bN * 128;

    float acc[2][8][4];
    #pragma unroll
    for (int mt = 0; mt < 2; mt++)
        #pragma unroll
        for (int j = 0; j < 8; j++)
            #pragma unroll
            for (int q = 0; q < 4; q++) acc[mt][j][q] = 0.f;

    const int a_row_l = (lane & 15);
    const int a_koff  = ((lane >> 4) << 3);
    const int b_krow  = (lane & 7) + ((lane >> 3) & 1) * 8;
    const int b_ncol  = ((lane >> 4) & 1) * 8;

    const int ar0 = tid >> 2, ac0 = tid & 3;
    const int kr0 = tid >> 4, c160 = tid & 15;

    auto issue = [&](int st, int k0) {
        uint32_t base = smb + st * X2_STAGE;
        #pragma unroll
        for (int i = 0; i < 2; i++) {
            int ar = (i == 0) ? ar0 : (ar0 + 64);
            int ac = ac0;
            size_t asrc = (aRowBase + ar) * DIM + k0 + ac * 8;
            cp16(base + ar * 80 + ac * 16, g_ahi + asrc);
            cp16(base + X2_A_BYTES + ar * 80 + ac * 16, g_alo + asrc);
            int kr = (i == 0) ? kr0 : (kr0 + 16);
            int c16 = c160;
            size_t wsrc = (size_t)(k0 + kr) * FOURH + wColBase + c16 * 8;
            cp16(base + 2 * X2_A_BYTES + kr * 272 + c16 * 16, g_whi + wsrc);
            cp16(base + 2 * X2_A_BYTES + X2_W_BYTES + kr * 272 + c16 * 16,
                 g_wlo + wsrc);
        }
    };

    issue(0, 0);  CP_COMMIT();
    issue(1, 32); CP_COMMIT();

    const int NSTAGE = DIM / 32;   // 16

    for (int s = 0; s < NSTAGE; s++) {
        CP_WAIT1();
        __syncthreads();

        if (s + 2 < NSTAGE) {
            issue((s + 2) % 3, (s + 2) * 32);
            CP_COMMIT();
        } else {
            CP_COMMIT();
        }

        uint32_t sAhi = smb + (s % 3) * X2_STAGE;
        uint32_t sAlo = sAhi + X2_A_BYTES;
        uint32_t sBhi = sAhi + 2 * X2_A_BYTES;
        uint32_t sBlo = sBhi + X2_W_BYTES;

        #pragma unroll
        for (int ks = 0; ks < 2; ks++) {
            const int kk0 = ks * 16;
            uint32_t aHi[2][4], aLo[2][4];
            #pragma unroll
            for (int mt = 0; mt < 2; mt++) {
                uint32_t off =
                    (uint32_t)((warpM * 32 + mt * 16 + a_row_l) * 40 + kk0 + a_koff) * 2;
                ldsm_x4(aHi[mt], sAhi + off);
                ldsm_x4(aLo[mt], sAlo + off);
            }
            // process B in two N-halves to cap live registers (~16 B-regs)
            #pragma unroll
            for (int nh = 0; nh < 2; nh++) {
                uint32_t bHi[2][4], bLo[2][4];
                #pragma unroll
                for (int nt2 = 0; nt2 < 2; nt2++) {
                    int nt = nh * 2 + nt2;
                    uint32_t off =
                        (uint32_t)((kk0 + b_krow) * 136 + warpN * 64 + nt * 16 + b_ncol) * 2;
                    ldsm_x4_t(bHi[nt2], sBhi + off);
                    ldsm_x4_t(bLo[nt2], sBlo + off);
                }
                #pragma unroll
                for (int mt = 0; mt < 2; mt++) {
                    #pragma unroll
                    for (int jj = 0; jj < 4; jj++) {
                        int j = nh * 4 + jj;
                        uint32_t bh0 = bHi[jj >> 1][(jj & 1) * 2];
                        uint32_t bh1 = bHi[jj >> 1][(jj & 1) * 2 + 1];
                        uint32_t bl0 = bLo[jj >> 1][(jj & 1) * 2];
                        uint32_t bl1 = bLo[jj >> 1][(jj & 1) * 2 + 1];
                        mma_bf16(acc[mt][j], aHi[mt], bh0, bh1);
                        mma_bf16(acc[mt][j], aHi[mt], bl0, bl1);
                        mma_bf16(acc[mt][j], aLo[mt], bh0, bh1);
                    }
                }
            }
        }
    }

    const int g  = lane >> 2;
    const int t2 = (lane & 3) * 2;
    #pragma unroll
    for (int mt = 0; mt < 2; mt++) {
        size_t row = aRowBase + warpM * 32 + mt * 16 + g;
        #pragma unroll
        for (int j = 0; j < 8; j++) {
            int col = (int)wColBase + warpN * 64 + j * 8 + t2;
            float b0 = bias[col], b1 = bias[col + 1];
            float2 o0 = make_float2(acc[mt][j][0] + b0, acc[mt][j][1] + b1);
            float2 o1 = make_float2(acc[mt][j][2] + b0, acc[mt][j][3] + b1);
            *(float2*)&g_xproj[row * FOURH + col] = o0;
            *(float2*)&g_xproj[(row + 8) * FOURH + col] = o1;
        }
    }
}

// ===========================================================================
// Kernel 2: recurrent kernel — UNCHANGED from R10 (bulk DSMEM + complete_tx).
// ===========================================================================
#define CLUSTER 8
#define NB      16
#define LC      128
#define RTHREADS 512

#define WSTRIDE 136
#define ZSTRIDE 140

#define HROW     80
#define LO_OFF   1280
#define RANK_BLK 2560
#define HBUF     (CLUSTER * RANK_BLK)

#define SMB_WHHI 0
#define SMB_WHLO (SMB_WHHI + 256 * WSTRIDE * 2)
#define SMB_HB   (SMB_WHLO + 256 * WSTRIDE * 2)
#define SMB_Z0   (SMB_HB + 2 * HBUF)
#define SMB_Z1   (SMB_Z0 + NB * ZSTRIDE * 4)
#define SMB_C    (SMB_Z1 + NB * ZSTRIDE * 4)
#define SMB_WO   (SMB_C + NB * 32 * 4)
#define SMB_BO   (SMB_WO + 5 * 256 * 4)
#define SMB_MBAR (SMB_BO + 32)
#define SMB_EP   (SMB_MBAR + 16)
#define RSMEM_BYTES (SMB_EP + T_STEPS * NB)

__device__ __forceinline__ void mbar_wait_cluster(uint32_t mbar, uint32_t parity) {
    uint32_t done;
    asm volatile(
        "{ .reg .pred p;\n"
        " mbarrier.try_wait.parity.acquire.cluster.shared::cta.b64 p, [%1], %2;\n"
        " selp.b32 %0, 1, 0, p; }"
        : "=r"(done) : "r"(mbar), "r"(parity) : "memory");
    while (!done) {
        asm volatile(
            "{ .reg .pred p;\n"
            " mbarrier.try_wait.parity.acquire.cluster.shared::cta.b64 p, [%1], %2, 0x989680;\n"
            " selp.b32 %0, 1, 0, p; }"
            : "=r"(done) : "r"(mbar), "r"(parity) : "memory");
    }
}

__device__ __forceinline__ void do_head(
    const char* hb,
    const float* Wo_s, const float* bo_s,
    float* out, int tt, int b0, int rank, int wid, int lane)
{
    float sacc[4];
    #pragma unroll
    for (int q = 0; q < 4; q++) {
        const float* wcol = &Wo_s[q * 256];
        float s = 0.f;
        #pragma unroll
        for (int uu = 0; uu < 8; uu++) {
            const char* blk = hb + uu * RANK_BLK + wid * HROW + lane * 2;
            float hv = __bfloat162float(*(const __nv_bfloat16*)blk)
                     + __bfloat162float(*(const __nv_bfloat16*)(blk + LO_OFF));
            s = fmaf(hv, wcol[lane + 32 * uu], s);
        }
        sacc[q] = s;
    }
    float sv = 0.f;
    if (rank == 0) {
        const float* wcol = &Wo_s[4 * 256];
        #pragma unroll
        for (int uu = 0; uu < 8; uu++) {
            const char* blk = hb + uu * RANK_BLK + wid * HROW + lane * 2;
            float hv = __bfloat162float(*(const __nv_bfloat16*)blk)
                     + __bfloat162float(*(const __nv_bfloat16*)(blk + LO_OFF));
            sv = fmaf(hv, wcol[lane + 32 * uu], sv);
        }
    }
    #pragma unroll
    for (int q = 0; q < 4; q++) {
        float s = sacc[q];
        #pragma unroll
        for (int off = 16; off; off >>= 1)
            s += __shfl_xor_sync(0xFFFFFFFFu, s, off);
        sacc[q] = s;
    }
    #pragma unroll
    for (int off = 16; off; off >>= 1)
        sv += __shfl_xor_sync(0xFFFFFFFFu, sv, off);
    if (lane == 0) {
        size_t obase = ((size_t)tt * BATCH + b0 + wid) * OUTC;
        #pragma unroll
        for (int q = 0; q < 4; q++)
            out[obase + rank + 8 * q] = sacc[q] + bo_s[q];
        if (rank == 0)
            out[obase + 32] = sv + bo_s[4];
    }
}

__global__ void __cluster_dims__(CLUSTER, 1, 1) __launch_bounds__(RTHREADS, 1)
lstm_rec_kernel(const int*   __restrict__ epi,
                const float* __restrict__ carry_c,
                const float* __restrict__ carry_h,
                const float* __restrict__ Wh,
                const float* __restrict__ Wa,
                const float* __restrict__ ba,
                const float* __restrict__ Wv,
                const float* __restrict__ bv,
                float*       __restrict__ out)
{
    extern __shared__ char smraw[];
    __nv_bfloat16* WhHi = (__nv_bfloat16*)(smraw + SMB_WHHI);
    __nv_bfloat16* WhLo = (__nv_bfloat16*)(smraw + SMB_WHLO);
    float* z0_s = (float*)(smraw + SMB_Z0);
    float* z1_s = (float*)(smraw + SMB_Z1);
    float* c_s  = (float*)(smraw + SMB_C);
    float* Wo_s = (float*)(smraw + SMB_WO);
    float* bo_s = (float*)(smraw + SMB_BO);
    unsigned char* ep_s = (unsigned char*)(smraw + SMB_EP);

    const int tid  = threadIdx.x;
    const int lane = tid & 31;
    const int wid  = tid >> 5;
    const int wn   = wid & 7;
    const int kh   = wid >> 3;
    uint32_t rank;
    asm("mov.u32 %0, %%cluster_ctarank;" : "=r"(rank));
    const int cl = blockIdx.x / CLUSTER;
    const int b0 = cl * NB;
    const uint32_t smbase = smem_u32(smraw);

    if (tid == 0) {
        asm volatile("mbarrier.init.shared.b64 [%0], %1;"
            :: "r"(smbase + SMB_MBAR), "r"(1u) : "memory");
        asm volatile("mbarrier.init.shared.b64 [%0], %1;"
            :: "r"(smbase + SMB_MBAR + 8), "r"(1u) : "memory");
    }

    for (int idx = tid; idx < 256 * LC; idx += RTHREADS) {
        int k = idx >> 7;
        int c = idx & 127;
        int gcol = ((c >> 5) << 8) + ((int)rank << 5) + (c & 31);
        float w = Wh[k * FOURH + gcol];
        __nv_bfloat16 hi = __float2bfloat16_rn(w);
        __nv_bfloat16 lo = __float2bfloat16_rn(w - __bfloat162float(hi));
        WhHi[k * WSTRIDE + c] = hi;
        WhLo[k * WSTRIDE + c] = lo;
    }
    for (int idx = tid; idx < 256 * 8; idx += RTHREADS) {
        int k = idx >> 3;
        int c = idx & 7;
        float w = 0.f;
        if (c < 4)                     w = Wa[k * NACT + (int)rank + 8 * c];
        else if (c == 4 && rank == 0)  w = Wv[k];
        __nv_bfloat16 hi = __float2bfloat16_rn(w);
        __nv_bfloat16 lo = __float2bfloat16_rn(w - __bfloat162float(hi));
        WhHi[k * WSTRIDE + 128 + c] = hi;
        WhLo[k * WSTRIDE + 128 + c] = lo;
    }
    for (int idx = tid; idx < NB * HID; idx += RTHREADS) {
        int b = idx >> 8;
        int k = idx & 255;
        float v = carry_h[(size_t)(b0 + b) * HID + k];
        __nv_bfloat16 hi = __float2bfloat16_rn(v);
        __nv_bfloat16 lo = __float2bfloat16_rn(v - __bfloat162float(hi));
        char* blk = smraw + SMB_HB + 1 * HBUF + (k >> 5) * RANK_BLK;
        *(__nv_bfloat16*)(blk + b * HROW + (k & 31) * 2) = hi;
        *(__nv_bfloat16*)(blk + LO_OFF + b * HROW + (k & 31) * 2) = lo;
    }
    for (int idx = tid; idx < NB * 32; idx += RTHREADS) {
        int b = idx >> 5;
        int j = idx & 31;
        c_s[idx] = carry_c[(size_t)(b0 + b) * HID + (int)rank * 32 + j];
    }
    #pragma unroll
    for (int q = 0; q < 5; q++) {
        int col = (int)rank + 8 * q;
        if (col <= 32) {
            for (int k = tid; k < HID; k += RTHREADS)
                Wo_s[q * 256 + k] = (col < 32) ? Wa[k * NACT + col] : Wv[k];
            if (tid == 0) bo_s[q] = (col < 32) ? ba[col] : bv[0];
        }
    }
    for (int idx = tid; idx < T_STEPS * NB; idx += RTHREADS) {
        int t = idx >> 4;
        int b = idx & 15;
        ep_s[idx] = (unsigned char)(epi[t * BATCH + b0 + b] != 0);
    }
    __syncthreads();
    asm volatile("barrier.cluster.arrive.aligned;" ::: "memory");
    asm volatile("barrier.cluster.wait.aligned;"   ::: "memory");

    const int a_row_l = (lane & 15);
    const int a_koff  = ((lane >> 4) << 3);
    const int b_krow  = (lane & 7) + ((lane >> 3) & 1) * 8;
    const int b_ncol  = ((lane >> 4) & 1) * 8;
    const int kbase   = kh * 128;

    const uint32_t sWhHi = smem_u32(WhHi);
    const uint32_t sWhLo = smem_u32(WhLo);
    float* zw_s = kh ? z1_s : z0_s;

    int ph0 = 0, ph1 = 0;

    const int gb = tid >> 5;
    const int gj = tid & 31;

    const int cp_peer = tid + (tid >= (int)rank);

    for (int t = 0; t < T_STEPS; t++) {
        const int p_out = t & 1;
        const int p_in  = p_out ^ 1;
        const uint32_t hinBase  = smbase + SMB_HB + (uint32_t)p_in * HBUF;
        char* houtB = smraw + SMB_HB + p_out * HBUF + (int)rank * RANK_BLK;

        if (tid == 0) {
            uint32_t mb = smbase + SMB_MBAR + (uint32_t)(((t + 1) & 1) * 8);
            asm volatile("mbarrier.arrive.expect_tx.shared.b64 _, [%0], %1;"
                :: "r"(mb), "r"((uint32_t)(7 * RANK_BLK)) : "memory");
        }

        const size_t xbase = (size_t)t * BATCH * FOURH
                           + (size_t)(b0 + gb) * FOURH + (int)rank * 32 + gj;
        float xi = g_xproj[xbase];
        float xf = g_xproj[xbase + 256];
        float xg = g_xproj[xbase + 512];
        float xo = g_xproj[xbase + 768];
        int   ep = ep_s[t * NB + gb];

        if (t > 0) {
            if (t & 1) { mbar_wait_cluster(smbase + SMB_MBAR + 8, ph1); ph1 ^= 1; }
            else       { mbar_wait_cluster(smbase + SMB_MBAR,     ph0); ph0 ^= 1; }
        }

        {
            float acc[2][4][4];
            float accH[2][4];
            #pragma unroll
            for (int t2 = 0; t2 < 2; t2++) {
                #pragma unroll
                for (int kc = 0; kc < 4; kc++)
                    #pragma unroll
                    for (int q = 0; q < 4; q++) acc[t2][kc][q] = 0.f;
                #pragma unroll
                for (int q = 0; q < 4; q++) accH[t2][q] = 0.f;
            }

            #pragma unroll
            for (int ks = 0; ks < 8; ks++) {
                const int kk0 = kbase + ks * 16;
                const int kc  = ks & 3;
                const int blk = kk0 >> 5;
                uint32_t aoff = hinBase + (uint32_t)(blk * RANK_BLK
                               + a_row_l * HROW + ((kk0 & 16) + a_koff) * 2);
                uint32_t aHi[4], aLo[4];
                ldsm_x4(aHi, aoff);
                ldsm_x4(aLo, aoff + LO_OFF);
                uint32_t boff =
                    (uint32_t)((kk0 + b_krow) * WSTRIDE + wn * 16 + b_ncol) * 2;
                uint32_t bHi[4], bLo[4];
                ldsm_x4_t(bHi, sWhHi + boff);
                ldsm_x4_t(bLo, sWhLo + boff);
                #pragma unroll
                for (int t2 = 0; t2 < 2; t2++) {
                    mma_bf16(acc[t2][kc], aHi, bHi[t2 * 2], bHi[t2 * 2 + 1]);
                    mma_bf16(acc[t2][kc], aHi, bLo[t2 * 2], bLo[t2 * 2 + 1]);
                    mma_bf16(acc[t2][kc], aLo, bHi[t2 * 2], bHi[t2 * 2 + 1]);
                }
                if (wn == 0) {
                    uint32_t hoff = (uint32_t)((kk0 + b_krow) * WSTRIDE + 128) * 2;
                    uint32_t hH[2], hL[2];
                    ldsm_x2_t(hH, sWhHi + hoff);
                    ldsm_x2_t(hL, sWhLo + hoff);
                    const int kc2 = ks & 1;
                    mma_bf16(accH[kc2], aHi, hH[0], hH[1]);
                    mma_bf16(accH[kc2], aHi, hL[0], hL[1]);
                    mma_bf16(accH[kc2], aLo, hH[0], hH[1]);
                }
            }
            int r0 = lane >> 2;
            int cb = wn * 16 + 2 * (lane & 3);
            #pragma unroll
            for (int t2 = 0; t2 < 2; t2++) {
                int col = cb + 8 * t2;
                float v0 = (acc[t2][0][0] + acc[t2][1][0]) + (acc[t2][2][0] + acc[t2][3][0]);
                float v1 = (acc[t2][0][1] + acc[t2][1][1]) + (acc[t2][2][1] + acc[t2][3][1]);
                float v2 = (acc[t2][0][2] + acc[t2][1][2]) + (acc[t2][2][2] + acc[t2][3][2]);
                float v3 = (acc[t2][0][3] + acc[t2][1][3]) + (acc[t2][2][3] + acc[t2][3][3]);
                *(float2*)&zw_s[r0 * ZSTRIDE + col] = make_float2(v0, v1);
                *(float2*)&zw_s[(r0 + 8) * ZSTRIDE + col] = make_float2(v2, v3);
            }
            if (wn == 0) {
                int colH = 128 + 2 * (lane & 3);
                float h0 = accH[0][0] + accH[1][0];
                float h1 = accH[0][1] + accH[1][1];
                float h2 = accH[0][2] + accH[1][2];
                float h3 = accH[0][3] + accH[1][3];
                *(float2*)&zw_s[r0 * ZSTRIDE + colH] = make_float2(h0, h1);
                *(float2*)&zw_s[(r0 + 8) * ZSTRIDE + colH] = make_float2(h2, h3);
            }
        }
        __syncthreads();

        if (t > 0) {
            if (tid < 64) {
                int b = tid >> 2, q = tid & 3;
                out[((size_t)(t - 1) * BATCH + b0 + b) * OUTC + (int)rank + 8 * q]
                    = z0_s[b * ZSTRIDE + 128 + q] + z1_s[b * ZSTRIDE + 128 + q] + bo_s[q];
            } else if (rank == 0 && tid < 80) {
                int b = tid - 64;
                out[((size_t)(t - 1) * BATCH + b0 + b) * OUTC + 32]
                    = z0_s[b * ZSTRIDE + 132] + z1_s[b * ZSTRIDE + 132] + bo_s[4];
            }
        }

        {
            float zi = z0_s[gb * ZSTRIDE + gj]      + z1_s[gb * ZSTRIDE + gj];
            float zf = z0_s[gb * ZSTRIDE + 32 + gj] + z1_s[gb * ZSTRIDE + 32 + gj];
            float zg = z0_s[gb * ZSTRIDE + 64 + gj] + z1_s[gb * ZSTRIDE + 64 + gj];
            float zo = z0_s[gb * ZSTRIDE + 96 + gj] + z1_s[gb * ZSTRIDE + 96 + gj];
            float c_old = c_s[gb * 32 + gj];
            if (ep) { zi = 0.f; zf = 0.f; zg = 0.f; zo = 0.f; c_old = 0.f; }
            float iz = zi + xi;
            float fz = zf + xf;
            float gz = zg + xg;
            float oz = zo + xo;
            float nc = fsig(fz) * c_old + fsig(iz) * ftanh(gz);
            float nh = fsig(oz) * ftanh(nc);
            c_s[gb * 32 + gj] = nc;
            __nv_bfloat16 hi = __float2bfloat16_rn(nh);
            __nv_bfloat16 lo = __float2bfloat16_rn(nh - __bfloat162float(hi));
            *(__nv_bfloat16*)(houtB + gb * HROW + gj * 2) = hi;
            *(__nv_bfloat16*)(houtB + LO_OFF + gb * HROW + gj * 2) = lo;
        }
        __syncthreads();

        if (tid < 7) {
            asm volatile("fence.proxy.async.shared::cta;" ::: "memory");
            uint32_t src = smbase + (uint32_t)(SMB_HB + p_out * HBUF
                                               + (int)rank * RANK_BLK);
            uint32_t dst, mb;
            asm("mapa.shared::cluster.u32 %0, %1, %2;"
                : "=r"(dst) : "r"(src), "r"(cp_peer));
            uint32_t mbl = smbase + SMB_MBAR + (uint32_t)(((t + 1) & 1) * 8);
            asm("mapa.shared::cluster.u32 %0, %1, %2;"
                : "=r"(mb) : "r"(mbl), "r"(cp_peer));
            asm volatile(
                "cp.async.bulk.shared::cluster.shared::cta.mbarrier::complete_tx::bytes "
                "[%0], [%1], %2, [%3];"
                :: "r"(dst), "r"(src), "r"((uint32_t)RANK_BLK), "r"(mb) : "memory");
        }
    }

    {
        mbar_wait_cluster(smbase + SMB_MBAR, ph0);
        do_head(smraw + SMB_HB + 1 * HBUF, Wo_s, bo_s, out,
                T_STEPS - 1, b0, (int)rank, wid, lane);
    }

    asm volatile("barrier.cluster.arrive.aligned;" ::: "memory");
    asm volatile("barrier.cluster.wait.aligned;"   ::: "memory");
}

// ---------------------------------------------------------------------------
extern "C" void kernel_launch(void* const* d_in, const int* in_sizes, int n_in,
                              void* d_out, int out_size) {
    const float* inputs  = (const float*)d_in[0];
    const int*   epi     = (const int*)  d_in[1];
    const float* carry_c = (const float*)d_in[2];
    const float* carry_h = (const float*)d_in[3];
    const float* Wx      = (const float*)d_in[4];
    const float* Wh      = (const float*)d_in[5];
    const float* bias    = (const float*)d_in[6];
    const float* Wa      = (const float*)d_in[7];
    const float* ba      = (const float*)d_in[8];
    const float* Wv      = (const float*)d_in[9];
    const float* bv      = (const float*)d_in[10];
    float* out = (float*)d_out;

    cudaFuncSetAttribute(xproj_mma_kernel,
                         cudaFuncAttributeMaxDynamicSharedMemorySize, X2_SMEM);
    cudaFuncSetAttribute(lstm_rec_kernel,
                         cudaFuncAttributeMaxDynamicSharedMemorySize, RSMEM_BYTES);

    split_kernel<<<2048, 256>>>(inputs, Wx);

    dim3 g1(FOURH / 128, M_ROWS / 128);   // (8, 1024)
    xproj_mma_kernel<<<g1, 256, X2_SMEM>>>(bias);

    lstm_rec_kernel<<<(BATCH / NB) * CLUSTER, RTHREADS, RSMEM_BYTES>>>(
        epi, carry_c, carry_h, Wh, Wa, ba, Wv, bv, out);
}

// round 15
// speedup vs baseline: 1.5433x; 1.0014x over previous
#include <cuda_runtime.h>
#include <cuda_bf16.h>
#include <cstdint>
#include <cstddef>

// Problem dims
#define T_STEPS 512
#define BATCH   256
#define DIM     512
#define HID     256
#define FOURH   1024
#define NACT    32
#define OUTC    33
#define M_ROWS  (T_STEPS * BATCH)   // 131072

// Global scratch
__device__ float g_xproj[(size_t)M_ROWS * FOURH];
__device__ __nv_bfloat16 g_ahi[(size_t)M_ROWS * DIM];
__device__ __nv_bfloat16 g_alo[(size_t)M_ROWS * DIM];
__device__ __nv_bfloat16 g_whi[(size_t)DIM * FOURH];
__device__ __nv_bfloat16 g_wlo[(size_t)DIM * FOURH];

// ===========================================================================
// Shared helpers
// ===========================================================================
__device__ __forceinline__ uint32_t smem_u32(const void* p) {
    uint32_t a;
    asm("{ .reg .u64 t; cvta.to.shared.u64 t, %1; cvt.u32.u64 %0, t; }"
        : "=r"(a) : "l"(p));
    return a;
}
__device__ __forceinline__ void ldsm_x4(uint32_t* r, uint32_t addr) {
    asm volatile("ldmatrix.sync.aligned.m8n8.x4.shared.b16 {%0,%1,%2,%3}, [%4];"
        : "=r"(r[0]), "=r"(r[1]), "=r"(r[2]), "=r"(r[3]) : "r"(addr));
}
__device__ __forceinline__ void ldsm_x4_t(uint32_t* r, uint32_t addr) {
    asm volatile("ldmatrix.sync.aligned.m8n8.x4.trans.shared.b16 {%0,%1,%2,%3}, [%4];"
        : "=r"(r[0]), "=r"(r[1]), "=r"(r[2]), "=r"(r[3]) : "r"(addr));
}
__device__ __forceinline__ void ldsm_x2_t(uint32_t* r, uint32_t addr) {
    asm volatile("ldmatrix.sync.aligned.m8n8.x2.trans.shared.b16 {%0,%1}, [%2];"
        : "=r"(r[0]), "=r"(r[1]) : "r"(addr));
}
__device__ __forceinline__ void mma_bf16(float* c, const uint32_t* a,
                                         uint32_t b0, uint32_t b1) {
    asm volatile(
        "mma.sync.aligned.m16n8k16.row.col.f32.bf16.bf16.f32 "
        "{%0,%1,%2,%3}, {%4,%5,%6,%7}, {%8,%9}, {%0,%1,%2,%3};"
        : "+f"(c[0]), "+f"(c[1]), "+f"(c[2]), "+f"(c[3])
        : "r"(a[0]), "r"(a[1]), "r"(a[2]), "r"(a[3]), "r"(b0), "r"(b1));
}
__device__ __forceinline__ uint32_t pack2(__nv_bfloat16 a, __nv_bfloat16 b) {
    union { __nv_bfloat162 v; uint32_t u; } c;
    c.v = __nv_bfloat162(a, b);
    return c.u;
}
__device__ __forceinline__ void split_store4(float4 v,
                                             __nv_bfloat16* hip,
                                             __nv_bfloat16* lop) {
    __nv_bfloat16 h0 = __float2bfloat16_rn(v.x);
    __nv_bfloat16 h1 = __float2bfloat16_rn(v.y);
    __nv_bfloat16 h2 = __float2bfloat16_rn(v.z);
    __nv_bfloat16 h3 = __float2bfloat16_rn(v.w);
    __nv_bfloat16 l0 = __float2bfloat16_rn(v.x - __bfloat162float(h0));
    __nv_bfloat16 l1 = __float2bfloat16_rn(v.y - __bfloat162float(h1));
    __nv_bfloat16 l2 = __float2bfloat16_rn(v.z - __bfloat162float(h2));
    __nv_bfloat16 l3 = __float2bfloat16_rn(v.w - __bfloat162float(h3));
    ((uint32_t*)hip)[0] = pack2(h0, h1);
    ((uint32_t*)hip)[1] = pack2(h2, h3);
    ((uint32_t*)lop)[0] = pack2(l0, l1);
    ((uint32_t*)lop)[1] = pack2(l2, l3);
}
__device__ __forceinline__ void cp16(uint32_t dst, const void* src) {
    asm volatile("cp.async.cg.shared.global [%0], [%1], 16;"
        :: "r"(dst), "l"(src) : "memory");
}
#define CP_COMMIT() asm volatile("cp.async.commit_group;" ::: "memory")
#define CP_WAIT0()  asm volatile("cp.async.wait_group 0;" ::: "memory")

// ---- MUFU-free activations ----
__device__ __forceinline__ float fast_exp(float x) {
    const float L2E = 1.4426950408889634f;
    float t  = fmaf(x, L2E, 12582912.0f);
    int   n  = __float_as_int(t) - 0x4B400000;
    float nf = t - 12582912.0f;
    float r  = fmaf(nf, -0.693359375f, x);
    r = fmaf(nf, 2.12194440e-4f, r);
    float p = 1.9841270e-4f;
    p = fmaf(p, r, 1.3888889e-3f);
    p = fmaf(p, r, 8.3333333e-3f);
    p = fmaf(p, r, 4.1666667e-2f);
    p = fmaf(p, r, 1.6666667e-1f);
    p = fmaf(p, r, 0.5f);
    p = fmaf(p, r, 1.0f);
    p = fmaf(p, r, 1.0f);
    return __int_as_float(__float_as_int(p) + (n << 23));
}
__device__ __forceinline__ float fast_rcp(float d) {
    float r = __int_as_float(0x7EF127EAu - __float_as_int(d));
    r = r * fmaf(-d, r, 2.0f);
    r = r * fmaf(-d, r, 2.0f);
    return r;
}
__device__ __forceinline__ float fsig(float x) {
    x = fminf(fmaxf(x, -30.0f), 30.0f);
    float e = fast_exp(-x);
    return fast_rcp(1.0f + e);
}
__device__ __forceinline__ float ftanh(float x) {
    return fmaf(2.0f, fsig(2.0f * x), -1.0f);
}

// ===========================================================================
// Kernel 0: split inputs + Wx into global bf16 hi/lo (memory-bound pre-pass)
// ===========================================================================
__global__ __launch_bounds__(256) void split_kernel(
    const float* __restrict__ A, const float* __restrict__ W)
{
    const size_t A4 = (size_t)M_ROWS * DIM / 4;
    const size_t W4 = (size_t)DIM * FOURH / 4;
    size_t stride = (size_t)gridDim.x * blockDim.x;
    for (size_t i = (size_t)blockIdx.x * blockDim.x + threadIdx.x;
         i < A4 + W4; i += stride) {
        float4 v;
        __nv_bfloat16 *hp, *lp;
        if (i < A4) {
            v = ((const float4*)A)[i];
            hp = g_ahi + i * 4;
            lp = g_alo + i * 4;
        } else {
            size_t j = i - A4;
            v = ((const float4*)W)[j];
            hp = g_whi + j * 4;
            lp = g_wlo + j * 4;
        }
        split_store4(v, hp, lp);
    }
}

// ===========================================================================
// Kernel 1: x_proj GEMM — pre-split bf16, cp.async DOUBLE-buffer pipeline.
// 2 stages x 37888 B = 75776 B smem/CTA -> 2 CTAs genuinely resident.
// Inner loop processes B in halves to stay under the 128-register cap.
// ===========================================================================
#define X2_A_BYTES (128 * 80)
#define X2_W_BYTES (32 * 272)
#define X2_STAGE   (2 * X2_A_BYTES + 2 * X2_W_BYTES)   // 37888
#define X2_SMEM    (2 * X2_STAGE)                       // 75776

__global__ __launch_bounds__(256, 2) void xproj_mma_kernel(
    const float* __restrict__ bias)
{
    extern __shared__ char xsm2[];
    const uint32_t smb = smem_u32(xsm2);

    const int tid   = threadIdx.x;
    const int lane  = tid & 31;
    const int wid   = tid >> 5;
    const int warpM = wid & 3;
    const int warpN = wid >> 2;
    const int bM    = blockIdx.y;
    const int bN    = blockIdx.x;

    const size_t aRowBase = (size_t)bM * 128;
    const size_t wColBase = (size_t)bN * 128;

    float acc[2][8][4];
    #pragma unroll
    for (int mt = 0; mt < 2; mt++)
        #pragma unroll
        for (int j = 0; j < 8; j++)
            #pragma unroll
            for (int q = 0; q < 4; q++) acc[mt][j][q] = 0.f;

    const int a_row_l = (lane & 15);
    const int a_koff  = ((lane >> 4) << 3);
    const int b_krow  = (lane & 7) + ((lane >> 3) & 1) * 8;
    const int b_ncol  = ((lane >> 4) & 1) * 8;

    const int ar0 = tid >> 2, ac0 = tid & 3;
    const int kr0 = tid >> 4, c160 = tid & 15;

    auto issue = [&](int st, int k0) {
        uint32_t base = smb + st * X2_STAGE;
        #pragma unroll
        for (int i = 0; i < 2; i++) {
            int ar = (i == 0) ? ar0 : (ar0 + 64);
            int ac = ac0;
            size_t asrc = (aRowBase + ar) * DIM + k0 + ac * 8;
            cp16(base + ar * 80 + ac * 16, g_ahi + asrc);
            cp16(base + X2_A_BYTES + ar * 80 + ac * 16, g_alo + asrc);
            int kr = (i == 0) ? kr0 : (kr0 + 16);
            int c16 = c160;
            size_t wsrc = (size_t)(k0 + kr) * FOURH + wColBase + c16 * 8;
            cp16(base + 2 * X2_A_BYTES + kr * 272 + c16 * 16, g_whi + wsrc);
            cp16(base + 2 * X2_A_BYTES + X2_W_BYTES + kr * 272 + c16 * 16,
                 g_wlo + wsrc);
        }
    };

    issue(0, 0);
    CP_COMMIT();

    const int NSTAGE = DIM / 32;   // 16

    for (int s = 0; s < NSTAGE; s++) {
        CP_WAIT0();
        __syncthreads();

        if (s + 1 < NSTAGE) {
            issue((s + 1) & 1, (s + 1) * 32);
            CP_COMMIT();
        }

        uint32_t sAhi = smb + (s & 1) * X2_STAGE;
        uint32_t sAlo = sAhi + X2_A_BYTES;
        uint32_t sBhi = sAhi + 2 * X2_A_BYTES;
        uint32_t sBlo = sBhi + X2_W_BYTES;

        #pragma unroll
        for (int ks = 0; ks < 2; ks++) {
            const int kk0 = ks * 16;
            uint32_t aHi[2][4], aLo[2][4];
            #pragma unroll
            for (int mt = 0; mt < 2; mt++) {
                uint32_t off =
                    (uint32_t)((warpM * 32 + mt * 16 + a_row_l) * 40 + kk0 + a_koff) * 2;
                ldsm_x4(aHi[mt], sAhi + off);
                ldsm_x4(aLo[mt], sAlo + off);
            }
            // process B in two N-halves to cap live registers
            #pragma unroll
            for (int nh = 0; nh < 2; nh++) {
                uint32_t bHi[2][4], bLo[2][4];
                #pragma unroll
                for (int nt2 = 0; nt2 < 2; nt2++) {
                    int nt = nh * 2 + nt2;
                    uint32_t off =
                        (uint32_t)((kk0 + b_krow) * 136 + warpN * 64 + nt * 16 + b_ncol) * 2;
                    ldsm_x4_t(bHi[nt2], sBhi + off);
                    ldsm_x4_t(bLo[nt2], sBlo + off);
                }
                #pragma unroll
                for (int mt = 0; mt < 2; mt++) {
                    #pragma unroll
                    for (int jj = 0; jj < 4; jj++) {
                        int j = nh * 4 + jj;
                        uint32_t bh0 = bHi[jj >> 1][(jj & 1) * 2];
                        uint32_t bh1 = bHi[jj >> 1][(jj & 1) * 2 + 1];
                        uint32_t bl0 = bLo[jj >> 1][(jj & 1) * 2];
                        uint32_t bl1 = bLo[jj >> 1][(jj & 1) * 2 + 1];
                        mma_bf16(acc[mt][j], aHi[mt], bh0, bh1);
                        mma_bf16(acc[mt][j], aHi[mt], bl0, bl1);
                        mma_bf16(acc[mt][j], aLo[mt], bh0, bh1);
                    }
                }
            }
        }
        __syncthreads();   // stage (s&1) fully consumed before next overwrite
    }

    const int g  = lane >> 2;
    const int t2 = (lane & 3) * 2;
    #pragma unroll
    for (int mt = 0; mt < 2; mt++) {
        size_t row = aRowBase + warpM * 32 + mt * 16 + g;
        #pragma unroll
        for (int j = 0; j < 8; j++) {
            int col = (int)wColBase + warpN * 64 + j * 8 + t2;
            float b0 = bias[col], b1 = bias[col + 1];
            float2 o0 = make_float2(acc[mt][j][0] + b0, acc[mt][j][1] + b1);
            float2 o1 = make_float2(acc[mt][j][2] + b0, acc[mt][j][3] + b1);
            *(float2*)&g_xproj[row * FOURH + col] = o0;
            *(float2*)&g_xproj[(row + 8) * FOURH + col] = o1;
        }
    }
}

// ===========================================================================
// Kernel 2: recurrent kernel — UNCHANGED from R10 (bulk DSMEM + complete_tx).
// ===========================================================================
#define CLUSTER 8
#define NB      16
#define LC      128
#define RTHREADS 512

#define WSTRIDE 136
#define ZSTRIDE 140

#define HROW     80
#define LO_OFF   1280
#define RANK_BLK 2560
#define HBUF     (CLUSTER * RANK_BLK)

#define SMB_WHHI 0
#define SMB_WHLO (SMB_WHHI + 256 * WSTRIDE * 2)
#define SMB_HB   (SMB_WHLO + 256 * WSTRIDE * 2)
#define SMB_Z0   (SMB_HB + 2 * HBUF)
#define SMB_Z1   (SMB_Z0 + NB * ZSTRIDE * 4)
#define SMB_C    (SMB_Z1 + NB * ZSTRIDE * 4)
#define SMB_WO   (SMB_C + NB * 32 * 4)
#define SMB_BO   (SMB_WO + 5 * 256 * 4)
#define SMB_MBAR (SMB_BO + 32)
#define SMB_EP   (SMB_MBAR + 16)
#define RSMEM_BYTES (SMB_EP + T_STEPS * NB)

__device__ __forceinline__ void mbar_wait_cluster(uint32_t mbar, uint32_t parity) {
    uint32_t done;
    asm volatile(
        "{ .reg .pred p;\n"
        " mbarrier.try_wait.parity.acquire.cluster.shared::cta.b64 p, [%1], %2;\n"
        " selp.b32 %0, 1, 0, p; }"
        : "=r"(done) : "r"(mbar), "r"(parity) : "memory");
    while (!done) {
        asm volatile(
            "{ .reg .pred p;\n"
            " mbarrier.try_wait.parity.acquire.cluster.shared::cta.b64 p, [%1], %2, 0x989680;\n"
            " selp.b32 %0, 1, 0, p; }"
            : "=r"(done) : "r"(mbar), "r"(parity) : "memory");
    }
}

__device__ __forceinline__ void do_head(
    const char* hb,
    const float* Wo_s, const float* bo_s,
    float* out, int tt, int b0, int rank, int wid, int lane)
{
    float sacc[4];
    #pragma unroll
    for (int q = 0; q < 4; q++) {
        const float* wcol = &Wo_s[q * 256];
        float s = 0.f;
        #pragma unroll
        for (int uu = 0; uu < 8; uu++) {
            const char* blk = hb + uu * RANK_BLK + wid * HROW + lane * 2;
            float hv = __bfloat162float(*(const __nv_bfloat16*)blk)
                     + __bfloat162float(*(const __nv_bfloat16*)(blk + LO_OFF));
            s = fmaf(hv, wcol[lane + 32 * uu], s);
        }
        sacc[q] = s;
    }
    float sv = 0.f;
    if (rank == 0) {
        const float* wcol = &Wo_s[4 * 256];
        #pragma unroll
        for (int uu = 0; uu < 8; uu++) {
            const char* blk = hb + uu * RANK_BLK + wid * HROW + lane * 2;
            float hv = __bfloat162float(*(const __nv_bfloat16*)blk)
                     + __bfloat162float(*(const __nv_bfloat16*)(blk + LO_OFF));
            sv = fmaf(hv, wcol[lane + 32 * uu], sv);
        }
    }
    #pragma unroll
    for (int q = 0; q < 4; q++) {
        float s = sacc[q];
        #pragma unroll
        for (int off = 16; off; off >>= 1)
            s += __shfl_xor_sync(0xFFFFFFFFu, s, off);
        sacc[q] = s;
    }
    #pragma unroll
    for (int off = 16; off; off >>= 1)
        sv += __shfl_xor_sync(0xFFFFFFFFu, sv, off);
    if (lane == 0) {
        size_t obase = ((size_t)tt * BATCH + b0 + wid) * OUTC;
        #pragma unroll
        for (int q = 0; q < 4; q++)
            out[obase + rank + 8 * q] = sacc[q] + bo_s[q];
        if (rank == 0)
            out[obase + 32] = sv + bo_s[4];
    }
}

__global__ void __cluster_dims__(CLUSTER, 1, 1) __launch_bounds__(RTHREADS, 1)
lstm_rec_kernel(const int*   __restrict__ epi,
                const float* __restrict__ carry_c,
                const float* __restrict__ carry_h,
                const float* __restrict__ Wh,
                const float* __restrict__ Wa,
                const float* __restrict__ ba,
                const float* __restrict__ Wv,
                const float* __restrict__ bv,
                float*       __restrict__ out)
{
    extern __shared__ char smraw[];
    __nv_bfloat16* WhHi = (__nv_bfloat16*)(smraw + SMB_WHHI);
    __nv_bfloat16* WhLo = (__nv_bfloat16*)(smraw + SMB_WHLO);
    float* z0_s = (float*)(smraw + SMB_Z0);
    float* z1_s = (float*)(smraw + SMB_Z1);
    float* c_s  = (float*)(smraw + SMB_C);
    float* Wo_s = (float*)(smraw + SMB_WO);
    float* bo_s = (float*)(smraw + SMB_BO);
    unsigned char* ep_s = (unsigned char*)(smraw + SMB_EP);

    const int tid  = threadIdx.x;
    const int lane = tid & 31;
    const int wid  = tid >> 5;
    const int wn   = wid & 7;
    const int kh   = wid >> 3;
    uint32_t rank;
    asm("mov.u32 %0, %%cluster_ctarank;" : "=r"(rank));
    const int cl = blockIdx.x / CLUSTER;
    const int b0 = cl * NB;
    const uint32_t smbase = smem_u32(smraw);

    if (tid == 0) {
        asm volatile("mbarrier.init.shared.b64 [%0], %1;"
            :: "r"(smbase + SMB_MBAR), "r"(1u) : "memory");
        asm volatile("mbarrier.init.shared.b64 [%0], %1;"
            :: "r"(smbase + SMB_MBAR + 8), "r"(1u) : "memory");
    }

    for (int idx = tid; idx < 256 * LC; idx += RTHREADS) {
        int k = idx >> 7;
        int c = idx & 127;
        int gcol = ((c >> 5) << 8) + ((int)rank << 5) + (c & 31);
        float w = Wh[k * FOURH + gcol];
        __nv_bfloat16 hi = __float2bfloat16_rn(w);
        __nv_bfloat16 lo = __float2bfloat16_rn(w - __bfloat162float(hi));
        WhHi[k * WSTRIDE + c] = hi;
        WhLo[k * WSTRIDE + c] = lo;
    }
    for (int idx = tid; idx < 256 * 8; idx += RTHREADS) {
        int k = idx >> 3;
        int c = idx & 7;
        float w = 0.f;
        if (c < 4)                     w = Wa[k * NACT + (int)rank + 8 * c];
        else if (c == 4 && rank == 0)  w = Wv[k];
        __nv_bfloat16 hi = __float2bfloat16_rn(w);
        __nv_bfloat16 lo = __float2bfloat16_rn(w - __bfloat162float(hi));
        WhHi[k * WSTRIDE + 128 + c] = hi;
        WhLo[k * WSTRIDE + 128 + c] = lo;
    }
    for (int idx = tid; idx < NB * HID; idx += RTHREADS) {
        int b = idx >> 8;
        int k = idx & 255;
        float v = carry_h[(size_t)(b0 + b) * HID + k];
        __nv_bfloat16 hi = __float2bfloat16_rn(v);
        __nv_bfloat16 lo = __float2bfloat16_rn(v - __bfloat162float(hi));
        char* blk = smraw + SMB_HB + 1 * HBUF + (k >> 5) * RANK_BLK;
        *(__nv_bfloat16*)(blk + b * HROW + (k & 31) * 2) = hi;
        *(__nv_bfloat16*)(blk + LO_OFF + b * HROW + (k & 31) * 2) = lo;
    }
    for (int idx = tid; idx < NB * 32; idx += RTHREADS) {
        int b = idx >> 5;
        int j = idx & 31;
        c_s[idx] = carry_c[(size_t)(b0 + b) * HID + (int)rank * 32 + j];
    }
    #pragma unroll
    for (int q = 0; q < 5; q++) {
        int col = (int)rank + 8 * q;
        if (col <= 32) {
            for (int k = tid; k < HID; k += RTHREADS)
                Wo_s[q * 256 + k] = (col < 32) ? Wa[k * NACT + col] : Wv[k];
            if (tid == 0) bo_s[q] = (col < 32) ? ba[col] : bv[0];
        }
    }
    for (int idx = tid; idx < T_STEPS * NB; idx += RTHREADS) {
        int t = idx >> 4;
        int b = idx & 15;
        ep_s[idx] = (unsigned char)(epi[t * BATCH + b0 + b] != 0);
    }
    __syncthreads();
    asm volatile("barrier.cluster.arrive.aligned;" ::: "memory");
    asm volatile("barrier.cluster.wait.aligned;"   ::: "memory");

    const int a_row_l = (lane & 15);
    const int a_koff  = ((lane >> 4) << 3);
    const int b_krow  = (lane & 7) + ((lane >> 3) & 1) * 8;
    const int b_ncol  = ((lane >> 4) & 1) * 8;
    const int kbase   = kh * 128;

    const uint32_t sWhHi = smem_u32(WhHi);
    const uint32_t sWhLo = smem_u32(WhLo);
    float* zw_s = kh ? z1_s : z0_s;

    int ph0 = 0, ph1 = 0;

    const int gb = tid >> 5;
    const int gj = tid & 31;

    const int cp_peer = tid + (tid >= (int)rank);

    for (int t = 0; t < T_STEPS; t++) {
        const int p_out = t & 1;
        const int p_in  = p_out ^ 1;
        const uint32_t hinBase  = smbase + SMB_HB + (uint32_t)p_in * HBUF;
        char* houtB = smraw + SMB_HB + p_out * HBUF + (int)rank * RANK_BLK;

        if (tid == 0) {
            uint32_t mb = smbase + SMB_MBAR + (uint32_t)(((t + 1) & 1) * 8);
            asm volatile("mbarrier.arrive.expect_tx.shared.b64 _, [%0], %1;"
                :: "r"(mb), "r"((uint32_t)(7 * RANK_BLK)) : "memory");
        }

        const size_t xbase = (size_t)t * BATCH * FOURH
                           + (size_t)(b0 + gb) * FOURH + (int)rank * 32 + gj;
        float xi = g_xproj[xbase];
        float xf = g_xproj[xbase + 256];
        float xg = g_xproj[xbase + 512];
        float xo = g_xproj[xbase + 768];
        int   ep = ep_s[t * NB + gb];

        if (t > 0) {
            if (t & 1) { mbar_wait_cluster(smbase + SMB_MBAR + 8, ph1); ph1 ^= 1; }
            else       { mbar_wait_cluster(smbase + SMB_MBAR,     ph0); ph0 ^= 1; }
        }

        {
            float acc[2][4][4];
            float accH[2][4];
            #pragma unroll
            for (int t2 = 0; t2 < 2; t2++) {
                #pragma unroll
                for (int kc = 0; kc < 4; kc++)
                    #pragma unroll
                    for (int q = 0; q < 4; q++) acc[t2][kc][q] = 0.f;
                #pragma unroll
                for (int q = 0; q < 4; q++) accH[t2][q] = 0.f;
            }

            #pragma unroll
            for (int ks = 0; ks < 8; ks++) {
                const int kk0 = kbase + ks * 16;
                const int kc  = ks & 3;
                const int blk = kk0 >> 5;
                uint32_t aoff = hinBase + (uint32_t)(blk * RANK_BLK
                               + a_row_l * HROW + ((kk0 & 16) + a_koff) * 2);
                uint32_t aHi[4], aLo[4];
                ldsm_x4(aHi, aoff);
                ldsm_x4(aLo, aoff + LO_OFF);
                uint32_t boff =
                    (uint32_t)((kk0 + b_krow) * WSTRIDE + wn * 16 + b_ncol) * 2;
                uint32_t bHi[4], bLo[4];
                ldsm_x4_t(bHi, sWhHi + boff);
                ldsm_x4_t(bLo, sWhLo + boff);
                #pragma unroll
                for (int t2 = 0; t2 < 2; t2++) {
                    mma_bf16(acc[t2][kc], aHi, bHi[t2 * 2], bHi[t2 * 2 + 1]);
                    mma_bf16(acc[t2][kc], aHi, bLo[t2 * 2], bLo[t2 * 2 + 1]);
                    mma_bf16(acc[t2][kc], aLo, bHi[t2 * 2], bHi[t2 * 2 + 1]);
                }
                if (wn == 0) {
                    uint32_t hoff = (uint32_t)((kk0 + b_krow) * WSTRIDE + 128) * 2;
                    uint32_t hH[2], hL[2];
                    ldsm_x2_t(hH, sWhHi + hoff);
                    ldsm_x2_t(hL, sWhLo + hoff);
                    const int kc2 = ks & 1;
                    mma_bf16(accH[kc2], aHi, hH[0], hH[1]);
                    mma_bf16(accH[kc2], aHi, hL[0], hL[1]);
                    mma_bf16(accH[kc2], aLo, hH[0], hH[1]);
                }
            }
            int r0 = lane >> 2;
            int cb = wn * 16 + 2 * (lane & 3);
            #pragma unroll
            for (int t2 = 0; t2 < 2; t2++) {
                int col = cb + 8 * t2;
                float v0 = (acc[t2][0][0] + acc[t2][1][0]) + (acc[t2][2][0] + acc[t2][3][0]);
                float v1 = (acc[t2][0][1] + acc[t2][1][1]) + (acc[t2][2][1] + acc[t2][3][1]);
                float v2 = (acc[t2][0][2] + acc[t2][1][2]) + (acc[t2][2][2] + acc[t2][3][2]);
                float v3 = (acc[t2][0][3] + acc[t2][1][3]) + (acc[t2][2][3] + acc[t2][3][3]);
                *(float2*)&zw_s[r0 * ZSTRIDE + col] = make_float2(v0, v1);
                *(float2*)&zw_s[(r0 + 8) * ZSTRIDE + col] = make_float2(v2, v3);
            }
            if (wn == 0) {
                int colH = 128 + 2 * (lane & 3);
                float h0 = accH[0][0] + accH[1][0];
                float h1 = accH[0][1] + accH[1][1];
                float h2 = accH[0][2] + accH[1][2];
                float h3 = accH[0][3] + accH[1][3];
                *(float2*)&zw_s[r0 * ZSTRIDE + colH] = make_float2(h0, h1);
                *(float2*)&zw_s[(r0 + 8) * ZSTRIDE + colH] = make_float2(h2, h3);
            }
        }
        __syncthreads();

        if (t > 0) {
            if (tid < 64) {
                int b = tid >> 2, q = tid & 3;
                out[((size_t)(t - 1) * BATCH + b0 + b) * OUTC + (int)rank + 8 * q]
                    = z0_s[b * ZSTRIDE + 128 + q] + z1_s[b * ZSTRIDE + 128 + q] + bo_s[q];
            } else if (rank == 0 && tid < 80) {
                int b = tid - 64;
                out[((size_t)(t - 1) * BATCH + b0 + b) * OUTC + 32]
                    = z0_s[b * ZSTRIDE + 132] + z1_s[b * ZSTRIDE + 132] + bo_s[4];
            }
        }

        {
            float zi = z0_s[gb * ZSTRIDE + gj]      + z1_s[gb * ZSTRIDE + gj];
            float zf = z0_s[gb * ZSTRIDE + 32 + gj] + z1_s[gb * ZSTRIDE + 32 + gj];
            float zg = z0_s[gb * ZSTRIDE + 64 + gj] + z1_s[gb * ZSTRIDE + 64 + gj];
            float zo = z0_s[gb * ZSTRIDE + 96 + gj] + z1_s[gb * ZSTRIDE + 96 + gj];
            float c_old = c_s[gb * 32 + gj];
            if (ep) { zi = 0.f; zf = 0.f; zg = 0.f; zo = 0.f; c_old = 0.f; }
            float iz = zi + xi;
            float fz = zf + xf;
            float gz = zg + xg;
            float oz = zo + xo;
            float nc = fsig(fz) * c_old + fsig(iz) * ftanh(gz);
            float nh = fsig(oz) * ftanh(nc);
            c_s[gb * 32 + gj] = nc;
            __nv_bfloat16 hi = __float2bfloat16_rn(nh);
            __nv_bfloat16 lo = __float2bfloat16_rn(nh - __bfloat162float(hi));
            *(__nv_bfloat16*)(houtB + gb * HROW + gj * 2) = hi;
            *(__nv_bfloat16*)(houtB + LO_OFF + gb * HROW + gj * 2) = lo;
        }
        __syncthreads();

        if (tid < 7) {
            asm volatile("fence.proxy.async.shared::cta;" ::: "memory");
            uint32_t src = smbase + (uint32_t)(SMB_HB + p_out * HBUF
                                               + (int)rank * RANK_BLK);
            uint32_t dst, mb;
            asm("mapa.shared::cluster.u32 %0, %1, %2;"
                : "=r"(dst) : "r"(src), "r"(cp_peer));
            uint32_t mbl = smbase + SMB_MBAR + (uint32_t)(((t + 1) & 1) * 8);
            asm("mapa.shared::cluster.u32 %0, %1, %2;"
                : "=r"(mb) : "r"(mbl), "r"(cp_peer));
            asm volatile(
                "cp.async.bulk.shared::cluster.shared::cta.mbarrier::complete_tx::bytes "
                "[%0], [%1], %2, [%3];"
                :: "r"(dst), "r"(src), "r"((uint32_t)RANK_BLK), "r"(mb) : "memory");
        }
    }

    {
        mbar_wait_cluster(smbase + SMB_MBAR, ph0);
        do_head(smraw + SMB_HB + 1 * HBUF, Wo_s, bo_s, out,
                T_STEPS - 1, b0, (int)rank, wid, lane);
    }

    asm volatile("barrier.cluster.arrive.aligned;" ::: "memory");
    asm volatile("barrier.cluster.wait.aligned;"   ::: "memory");
}

// ---------------------------------------------------------------------------
extern "C" void kernel_launch(void* const* d_in, const int* in_sizes, int n_in,
                              void* d_out, int out_size) {
    const float* inputs  = (const float*)d_in[0];
    const int*   epi     = (const int*)  d_in[1];
    const float* carry_c = (const float*)d_in[2];
    const float* carry_h = (const float*)d_in[3];
    const float* Wx      = (const float*)d_in[4];
    const float* Wh      = (const float*)d_in[5];
    const float* bias    = (const float*)d_in[6];
    const float* Wa      = (const float*)d_in[7];
    const float* ba      = (const float*)d_in[8];
    const float* Wv      = (const float*)d_in[9];
    const float* bv      = (const float*)d_in[10];
    float* out = (float*)d_out;

    cudaFuncSetAttribute(xproj_mma_kernel,
                         cudaFuncAttributeMaxDynamicSharedMemorySize, X2_SMEM);
    cudaFuncSetAttribute(lstm_rec_kernel,
                         cudaFuncAttributeMaxDynamicSharedMemorySize, RSMEM_BYTES);

    split_kernel<<<2048, 256>>>(inputs, Wx);

    dim3 g1(FOURH / 128, M_ROWS / 128);   // (8, 1024)
    xproj_mma_kernel<<<g1, 256, X2_SMEM>>>(bias);

    lstm_rec_kernel<<<(BATCH / NB) * CLUSTER, RTHREADS, RSMEM_BYTES>>>(
        epi, carry_c, carry_h, Wh, Wa, ba, Wv, bv, out);
}

// round 17
// speedup vs baseline: 1.6261x; 1.0536x over previous
#include <cuda_runtime.h>
#include <cuda_bf16.h>
#include <cstdint>
#include <cstddef>

// Problem dims
#define T_STEPS 512
#define BATCH   256
#define DIM     512
#define HID     256
#define FOURH   1024
#define NACT    32
#define OUTC    33
#define M_ROWS  (T_STEPS * BATCH)   // 131072

// Global scratch
__device__ float g_xproj[(size_t)M_ROWS * FOURH];
__device__ __nv_bfloat16 g_ahi[(size_t)M_ROWS * DIM];
__device__ __nv_bfloat16 g_alo[(size_t)M_ROWS * DIM];
__device__ __nv_bfloat16 g_whi[(size_t)DIM * FOURH];
__device__ __nv_bfloat16 g_wlo[(size_t)DIM * FOURH];

// ===========================================================================
// Shared helpers
// ===========================================================================
__device__ __forceinline__ uint32_t smem_u32(const void* p) {
    uint32_t a;
    asm("{ .reg .u64 t; cvta.to.shared.u64 t, %1; cvt.u32.u64 %0, t; }"
        : "=r"(a) : "l"(p));
    return a;
}
__device__ __forceinline__ void ldsm_x4(uint32_t* r, uint32_t addr) {
    asm volatile("ldmatrix.sync.aligned.m8n8.x4.shared.b16 {%0,%1,%2,%3}, [%4];"
        : "=r"(r[0]), "=r"(r[1]), "=r"(r[2]), "=r"(r[3]) : "r"(addr));
}
__device__ __forceinline__ void ldsm_x4_t(uint32_t* r, uint32_t addr) {
    asm volatile("ldmatrix.sync.aligned.m8n8.x4.trans.shared.b16 {%0,%1,%2,%3}, [%4];"
        : "=r"(r[0]), "=r"(r[1]), "=r"(r[2]), "=r"(r[3]) : "r"(addr));
}
__device__ __forceinline__ void ldsm_x2_t(uint32_t* r, uint32_t addr) {
    asm volatile("ldmatrix.sync.aligned.m8n8.x2.trans.shared.b16 {%0,%1}, [%2];"
        : "=r"(r[0]), "=r"(r[1]) : "r"(addr));
}
__device__ __forceinline__ void mma_bf16(float* c, const uint32_t* a,
                                         uint32_t b0, uint32_t b1) {
    asm volatile(
        "mma.sync.aligned.m16n8k16.row.col.f32.bf16.bf16.f32 "
        "{%0,%1,%2,%3}, {%4,%5,%6,%7}, {%8,%9}, {%0,%1,%2,%3};"
        : "+f"(c[0]), "+f"(c[1]), "+f"(c[2]), "+f"(c[3])
        : "r"(a[0]), "r"(a[1]), "r"(a[2]), "r"(a[3]), "r"(b0), "r"(b1));
}
__device__ __forceinline__ uint32_t pack2(__nv_bfloat16 a, __nv_bfloat16 b) {
    union { __nv_bfloat162 v; uint32_t u; } c;
    c.v = __nv_bfloat162(a, b);
    return c.u;
}
__device__ __forceinline__ void split_store4(float4 v,
                                             __nv_bfloat16* hip,
                                             __nv_bfloat16* lop) {
    __nv_bfloat16 h0 = __float2bfloat16_rn(v.x);
    __nv_bfloat16 h1 = __float2bfloat16_rn(v.y);
    __nv_bfloat16 h2 = __float2bfloat16_rn(v.z);
    __nv_bfloat16 h3 = __float2bfloat16_rn(v.w);
    __nv_bfloat16 l0 = __float2bfloat16_rn(v.x - __bfloat162float(h0));
    __nv_bfloat16 l1 = __float2bfloat16_rn(v.y - __bfloat162float(h1));
    __nv_bfloat16 l2 = __float2bfloat16_rn(v.z - __bfloat162float(h2));
    __nv_bfloat16 l3 = __float2bfloat16_rn(v.w - __bfloat162float(h3));
    ((uint32_t*)hip)[0] = pack2(h0, h1);
    ((uint32_t*)hip)[1] = pack2(h2, h3);
    ((uint32_t*)lop)[0] = pack2(l0, l1);
    ((uint32_t*)lop)[1] = pack2(l2, l3);
}
__device__ __forceinline__ void cp16(uint32_t dst, const void* src) {
    asm volatile("cp.async.cg.shared.global [%0], [%1], 16;"
        :: "r"(dst), "l"(src) : "memory");
}
#define CP_COMMIT() asm volatile("cp.async.commit_group;" ::: "memory")
#define CP_WAIT0()  asm volatile("cp.async.wait_group 0;" ::: "memory")

// ---- MUFU-free activations ----
__device__ __forceinline__ float fast_exp(float x) {
    const float L2E = 1.4426950408889634f;
    float t  = fmaf(x, L2E, 12582912.0f);
    int   n  = __float_as_int(t) - 0x4B400000;
    float nf = t - 12582912.0f;
    float r  = fmaf(nf, -0.693359375f, x);
    r = fmaf(nf, 2.12194440e-4f, r);
    float p = 1.9841270e-4f;
    p = fmaf(p, r, 1.3888889e-3f);
    p = fmaf(p, r, 8.3333333e-3f);
    p = fmaf(p, r, 4.1666667e-2f);
    p = fmaf(p, r, 1.6666667e-1f);
    p = fmaf(p, r, 0.5f);
    p = fmaf(p, r, 1.0f);
    p = fmaf(p, r, 1.0f);
    return __int_as_float(__float_as_int(p) + (n << 23));
}
__device__ __forceinline__ float fast_rcp(float d) {
    float r = __int_as_float(0x7EF127EAu - __float_as_int(d));
    r = r * fmaf(-d, r, 2.0f);
    r = r * fmaf(-d, r, 2.0f);
    return r;
}
__device__ __forceinline__ float fsig(float x) {
    x = fminf(fmaxf(x, -30.0f), 30.0f);
    float e = fast_exp(-x);
    return fast_rcp(1.0f + e);
}
__device__ __forceinline__ float ftanh(float x) {
    return fmaf(2.0f, fsig(2.0f * x), -1.0f);
}

// ===========================================================================
// Kernel 0: split inputs + Wx into global bf16 hi/lo (memory-bound pre-pass)
// ===========================================================================
__global__ __launch_bounds__(256) void split_kernel(
    const float* __restrict__ A, const float* __restrict__ W)
{
    const size_t A4 = (size_t)M_ROWS * DIM / 4;
    const size_t W4 = (size_t)DIM * FOURH / 4;
    size_t stride = (size_t)gridDim.x * blockDim.x;
    for (size_t i = (size_t)blockIdx.x * blockDim.x + threadIdx.x;
         i < A4 + W4; i += stride) {
        float4 v;
        __nv_bfloat16 *hp, *lp;
        if (i < A4) {
            v = ((const float4*)A)[i];
            hp = g_ahi + i * 4;
            lp = g_alo + i * 4;
        } else {
            size_t j = i - A4;
            v = ((const float4*)W)[j];
            hp = g_whi + j * 4;
            lp = g_wlo + j * 4;
        }
        split_store4(v, hp, lp);
    }
}

// ===========================================================================
// Kernel 1: x_proj GEMM — pre-split bf16, cp.async double-buffer (R15, passed)
// ===========================================================================
#define X2_A_BYTES (128 * 80)
#define X2_W_BYTES (32 * 272)
#define X2_STAGE   (2 * X2_A_BYTES + 2 * X2_W_BYTES)   // 37888
#define X2_SMEM    (2 * X2_STAGE)                       // 75776

__global__ __launch_bounds__(256, 2) void xproj_mma_kernel(
    const float* __restrict__ bias)
{
    extern __shared__ char xsm2[];
    const uint32_t smb = smem_u32(xsm2);

    const int tid   = threadIdx.x;
    const int lane  = tid & 31;
    const int wid   = tid >> 5;
    const int warpM = wid & 3;
    const int warpN = wid >> 2;
    const int bM    = blockIdx.y;
    const int bN    = blockIdx.x;

    const size_t aRowBase = (size_t)bM * 128;
    const size_t wColBase = (size_t)bN * 128;

    float acc[2][8][4];
    #pragma unroll
    for (int mt = 0; mt < 2; mt++)
        #pragma unroll
        for (int j = 0; j < 8; j++)
            #pragma unroll
            for (int q = 0; q < 4; q++) acc[mt][j][q] = 0.f;

    const int a_row_l = (lane & 15);
    const int a_koff  = ((lane >> 4) << 3);
    const int b_krow  = (lane & 7) + ((lane >> 3) & 1) * 8;
    const int b_ncol  = ((lane >> 4) & 1) * 8;

    const int ar0 = tid >> 2, ac0 = tid & 3;
    const int kr0 = tid >> 4, c160 = tid & 15;

    auto issue = [&](int st, int k0) {
        uint32_t base = smb + st * X2_STAGE;
        #pragma unroll
        for (int i = 0; i < 2; i++) {
            int ar = (i == 0) ? ar0 : (ar0 + 64);
            int ac = ac0;
            size_t asrc = (aRowBase + ar) * DIM + k0 + ac * 8;
            cp16(base + ar * 80 + ac * 16, g_ahi + asrc);
            cp16(base + X2_A_BYTES + ar * 80 + ac * 16, g_alo + asrc);
            int kr = (i == 0) ? kr0 : (kr0 + 16);
            int c16 = c160;
            size_t wsrc = (size_t)(k0 + kr) * FOURH + wColBase + c16 * 8;
            cp16(base + 2 * X2_A_BYTES + kr * 272 + c16 * 16, g_whi + wsrc);
            cp16(base + 2 * X2_A_BYTES + X2_W_BYTES + kr * 272 + c16 * 16,
                 g_wlo + wsrc);
        }
    };

    issue(0, 0);
    CP_COMMIT();

    const int NSTAGE = DIM / 32;   // 16

    for (int s = 0; s < NSTAGE; s++) {
        CP_WAIT0();
        __syncthreads();

        if (s + 1 < NSTAGE) {
            issue((s + 1) & 1, (s + 1) * 32);
            CP_COMMIT();
        }

        uint32_t sAhi = smb + (s & 1) * X2_STAGE;
        uint32_t sAlo = sAhi + X2_A_BYTES;
        uint32_t sBhi = sAhi + 2 * X2_A_BYTES;
        uint32_t sBlo = sBhi + X2_W_BYTES;

        #pragma unroll
        for (int ks = 0; ks < 2; ks++) {
            const int kk0 = ks * 16;
            uint32_t aHi[2][4], aLo[2][4];
            #pragma unroll
            for (int mt = 0; mt < 2; mt++) {
                uint32_t off =
                    (uint32_t)((warpM * 32 + mt * 16 + a_row_l) * 40 + kk0 + a_koff) * 2;
                ldsm_x4(aHi[mt], sAhi + off);
                ldsm_x4(aLo[mt], sAlo + off);
            }
            #pragma unroll
            for (int nh = 0; nh < 2; nh++) {
                uint32_t bHi[2][4], bLo[2][4];
                #pragma unroll
                for (int nt2 = 0; nt2 < 2; nt2++) {
                    int nt = nh * 2 + nt2;
                    uint32_t off =
                        (uint32_t)((kk0 + b_krow) * 136 + warpN * 64 + nt * 16 + b_ncol) * 2;
                    ldsm_x4_t(bHi[nt2], sBhi + off);
                    ldsm_x4_t(bLo[nt2], sBlo + off);
                }
                #pragma unroll
                for (int mt = 0; mt < 2; mt++) {
                    #pragma unroll
                    for (int jj = 0; jj < 4; jj++) {
                        int j = nh * 4 + jj;
                        uint32_t bh0 = bHi[jj >> 1][(jj & 1) * 2];
                        uint32_t bh1 = bHi[jj >> 1][(jj & 1) * 2 + 1];
                        uint32_t bl0 = bLo[jj >> 1][(jj & 1) * 2];
                        uint32_t bl1 = bLo[jj >> 1][(jj & 1) * 2 + 1];
                        mma_bf16(acc[mt][j], aHi[mt], bh0, bh1);
                        mma_bf16(acc[mt][j], aHi[mt], bl0, bl1);
                        mma_bf16(acc[mt][j], aLo[mt], bh0, bh1);
                    }
                }
            }
        }
        __syncthreads();
    }

    const int g  = lane >> 2;
    const int t2 = (lane & 3) * 2;
    #pragma unroll
    for (int mt = 0; mt < 2; mt++) {
        size_t row = aRowBase + warpM * 32 + mt * 16 + g;
        #pragma unroll
        for (int j = 0; j < 8; j++) {
            int col = (int)wColBase + warpN * 64 + j * 8 + t2;
            float b0 = bias[col], b1 = bias[col + 1];
            float2 o0 = make_float2(acc[mt][j][0] + b0, acc[mt][j][1] + b1);
            float2 o1 = make_float2(acc[mt][j][2] + b0, acc[mt][j][3] + b1);
            *(float2*)&g_xproj[row * FOURH + col] = o0;
            *(float2*)&g_xproj[(row + 8) * FOURH + col] = o1;
        }
    }
}

// ===========================================================================
// Kernel 2: recurrent kernel — split-half arrival barriers:
// barrier A <- sender ranks 0-3 (k 0..127), barrier B <- ranks 4-7.
// kh=0 warps wait A only; kh=1 warps wait B only.
// ===========================================================================
#define CLUSTER 8
#define NB      16
#define LC      128
#define RTHREADS 512

#define WSTRIDE 136
#define ZSTRIDE 140

#define HROW     80
#define LO_OFF   1280
#define RANK_BLK 2560
#define HBUF     (CLUSTER * RANK_BLK)

#define SMB_WHHI 0
#define SMB_WHLO (SMB_WHHI + 256 * WSTRIDE * 2)
#define SMB_HB   (SMB_WHLO + 256 * WSTRIDE * 2)
#define SMB_Z0   (SMB_HB + 2 * HBUF)
#define SMB_Z1   (SMB_Z0 + NB * ZSTRIDE * 4)
#define SMB_C    (SMB_Z1 + NB * ZSTRIDE * 4)
#define SMB_WO   (SMB_C + NB * 32 * 4)
#define SMB_BO   (SMB_WO + 5 * 256 * 4)
#define SMB_MBAR (SMB_BO + 32)            // 4 x 8B: [ph0A, ph0B, ph1A, ph1B]
#define SMB_EP   (SMB_MBAR + 32)
#define RSMEM_BYTES (SMB_EP + T_STEPS * NB)

__device__ __forceinline__ void mbar_wait_cluster(uint32_t mbar, uint32_t parity) {
    uint32_t done;
    asm volatile(
        "{ .reg .pred p;\n"
        " mbarrier.try_wait.parity.acquire.cluster.shared::cta.b64 p, [%1], %2;\n"
        " selp.b32 %0, 1, 0, p; }"
        : "=r"(done) : "r"(mbar), "r"(parity) : "memory");
    while (!done) {
        asm volatile(
            "{ .reg .pred p;\n"
            " mbarrier.try_wait.parity.acquire.cluster.shared::cta.b64 p, [%1], %2, 0x989680;\n"
            " selp.b32 %0, 1, 0, p; }"
            : "=r"(done) : "r"(mbar), "r"(parity) : "memory");
    }
}

__device__ __forceinline__ void do_head(
    const char* hb,
    const float* Wo_s, const float* bo_s,
    float* out, int tt, int b0, int rank, int wid, int lane)
{
    float sacc[4];
    #pragma unroll
    for (int q = 0; q < 4; q++) {
        const float* wcol = &Wo_s[q * 256];
        float s = 0.f;
        #pragma unroll
        for (int uu = 0; uu < 8; uu++) {
            const char* blk = hb + uu * RANK_BLK + wid * HROW + lane * 2;
            float hv = __bfloat162float(*(const __nv_bfloat16*)blk)
                     + __bfloat162float(*(const __nv_bfloat16*)(blk + LO_OFF));
            s = fmaf(hv, wcol[lane + 32 * uu], s);
        }
        sacc[q] = s;
    }
    float sv = 0.f;
    if (rank == 0) {
        const float* wcol = &Wo_s[4 * 256];
        #pragma unroll
        for (int uu = 0; uu < 8; uu++) {
            const char* blk = hb + uu * RANK_BLK + wid * HROW + lane * 2;
            float hv = __bfloat162float(*(const __nv_bfloat16*)blk)
                     + __bfloat162float(*(const __nv_bfloat16*)(blk + LO_OFF));
            sv = fmaf(hv, wcol[lane + 32 * uu], sv);
        }
    }
    #pragma unroll
    for (int q = 0; q < 4; q++) {
        float s = sacc[q];
        #pragma unroll
        for (int off = 16; off; off >>= 1)
            s += __shfl_xor_sync(0xFFFFFFFFu, s, off);
        sacc[q] = s;
    }
    #pragma unroll
    for (int off = 16; off; off >>= 1)
        sv += __shfl_xor_sync(0xFFFFFFFFu, sv, off);
    if (lane == 0) {
        size_t obase = ((size_t)tt * BATCH + b0 + wid) * OUTC;
        #pragma unroll
        for (int q = 0; q < 4; q++)
            out[obase + rank + 8 * q] = sacc[q] + bo_s[q];
        if (rank == 0)
            out[obase + 32] = sv + bo_s[4];
    }
}

__global__ void __cluster_dims__(CLUSTER, 1, 1) __launch_bounds__(RTHREADS, 1)
lstm_rec_kernel(const int*   __restrict__ epi,
                const float* __restrict__ carry_c,
                const float* __restrict__ carry_h,
                const float* __restrict__ Wh,
                const float* __restrict__ Wa,
                const float* __restrict__ ba,
                const float* __restrict__ Wv,
                const float* __restrict__ bv,
                float*       __restrict__ out)
{
    extern __shared__ char smraw[];
    __nv_bfloat16* WhHi = (__nv_bfloat16*)(smraw + SMB_WHHI);
    __nv_bfloat16* WhLo = (__nv_bfloat16*)(smraw + SMB_WHLO);
    float* z0_s = (float*)(smraw + SMB_Z0);
    float* z1_s = (float*)(smraw + SMB_Z1);
    float* c_s  = (float*)(smraw + SMB_C);
    float* Wo_s = (float*)(smraw + SMB_WO);
    float* bo_s = (float*)(smraw + SMB_BO);
    unsigned char* ep_s = (unsigned char*)(smraw + SMB_EP);

    const int tid  = threadIdx.x;
    const int lane = tid & 31;
    const int wid  = tid >> 5;
    const int wn   = wid & 7;
    const int kh   = wid >> 3;
    uint32_t rank;
    asm("mov.u32 %0, %%cluster_ctarank;" : "=r"(rank));
    const int cl = blockIdx.x / CLUSTER;
    const int b0 = cl * NB;
    const uint32_t smbase = smem_u32(smraw);

    // --- init 4 mbarriers (count = 1: the local expect_tx arrival) ---
    if (tid == 0) {
        #pragma unroll
        for (int b = 0; b < 4; b++)
            asm volatile("mbarrier.init.shared.b64 [%0], %1;"
                :: "r"(smbase + SMB_MBAR + b * 8), "r"(1u) : "memory");
    }

    for (int idx = tid; idx < 256 * LC; idx += RTHREADS) {
        int k = idx >> 7;
        int c = idx & 127;
        int gcol = ((c >> 5) << 8) + ((int)rank << 5) + (c & 31);
        float w = Wh[k * FOURH + gcol];
        __nv_bfloat16 hi = __float2bfloat16_rn(w);
        __nv_bfloat16 lo = __float2bfloat16_rn(w - __bfloat162float(hi));
        WhHi[k * WSTRIDE + c] = hi;
        WhLo[k * WSTRIDE + c] = lo;
    }
    for (int idx = tid; idx < 256 * 8; idx += RTHREADS) {
        int k = idx >> 3;
        int c = idx & 7;
        float w = 0.f;
        if (c < 4)                     w = Wa[k * NACT + (int)rank + 8 * c];
        else if (c == 4 && rank == 0)  w = Wv[k];
        __nv_bfloat16 hi = __float2bfloat16_rn(w);
        __nv_bfloat16 lo = __float2bfloat16_rn(w - __bfloat162float(hi));
        WhHi[k * WSTRIDE + 128 + c] = hi;
        WhLo[k * WSTRIDE + 128 + c] = lo;
    }
    for (int idx = tid; idx < NB * HID; idx += RTHREADS) {
        int b = idx >> 8;
        int k = idx & 255;
        float v = carry_h[(size_t)(b0 + b) * HID + k];
        __nv_bfloat16 hi = __float2bfloat16_rn(v);
        __nv_bfloat16 lo = __float2bfloat16_rn(v - __bfloat162float(hi));
        char* blk = smraw + SMB_HB + 1 * HBUF + (k >> 5) * RANK_BLK;
        *(__nv_bfloat16*)(blk + b * HROW + (k & 31) * 2) = hi;
        *(__nv_bfloat16*)(blk + LO_OFF + b * HROW + (k & 31) * 2) = lo;
    }
    for (int idx = tid; idx < NB * 32; idx += RTHREADS) {
        int b = idx >> 5;
        int j = idx & 31;
        c_s[idx] = carry_c[(size_t)(b0 + b) * HID + (int)rank * 32 + j];
    }
    #pragma unroll
    for (int q = 0; q < 5; q++) {
        int col = (int)rank + 8 * q;
        if (col <= 32) {
            for (int k = tid; k < HID; k += RTHREADS)
                Wo_s[q * 256 + k] = (col < 32) ? Wa[k * NACT + col] : Wv[k];
            if (tid == 0) bo_s[q] = (col < 32) ? ba[col] : bv[0];
        }
    }
    for (int idx = tid; idx < T_STEPS * NB; idx += RTHREADS) {
        int t = idx >> 4;
        int b = idx & 15;
        ep_s[idx] = (unsigned char)(epi[t * BATCH + b0 + b] != 0);
    }
    __syncthreads();
    asm volatile("barrier.cluster.arrive.aligned;" ::: "memory");
    asm volatile("barrier.cluster.wait.aligned;"   ::: "memory");

    const int a_row_l = (lane & 15);
    const int a_koff  = ((lane >> 4) << 3);
    const int b_krow  = (lane & 7) + ((lane >> 3) & 1) * 8;
    const int b_ncol  = ((lane >> 4) & 1) * 8;
    const int kbase   = kh * 128;

    const uint32_t sWhHi = smem_u32(WhHi);
    const uint32_t sWhLo = smem_u32(WhLo);
    float* zw_s = kh ? z1_s : z0_s;

    int ph0 = 0, ph1 = 0;

    const int gb = tid >> 5;
    const int gj = tid & 31;

    const int cp_peer = tid + (tid >= (int)rank);
    const uint32_t my_half_off = (rank >= 4) ? 8u : 0u;   // sender's dst barrier
    // arming byte counts: A <- ranks 0..3 minus self; B <- ranks 4..7 minus self
    const uint32_t cntA = RANK_BLK * ((rank < 4) ? 3u : 4u);
    const uint32_t cntB = RANK_BLK * ((rank < 4) ? 4u : 3u);

    for (int t = 0; t < T_STEPS; t++) {
        const int p_out = t & 1;
        const int p_in  = p_out ^ 1;
        const uint32_t hinBase  = smbase + SMB_HB + (uint32_t)p_in * HBUF;
        char* houtB = smraw + SMB_HB + p_out * HBUF + (int)rank * RANK_BLK;

        // -- arm both half-barriers for step t+1 data --
        if (tid < 2) {
            uint32_t mb = smbase + SMB_MBAR + (uint32_t)(((t + 1) & 1) * 16)
                        + (uint32_t)tid * 8;
            uint32_t cnt = (tid == 0) ? cntA : cntB;
            asm volatile("mbarrier.arrive.expect_tx.shared.b64 _, [%0], %1;"
                :: "r"(mb), "r"(cnt) : "memory");
        }

        const size_t xbase = (size_t)t * BATCH * FOURH
                           + (size_t)(b0 + gb) * FOURH + (int)rank * 32 + gj;
        float xi = g_xproj[xbase];
        float xf = g_xproj[xbase + 256];
        float xg = g_xproj[xbase + 512];
        float xo = g_xproj[xbase + 768];
        int   ep = ep_s[t * NB + gb];

        // -- wait only this warp's K-half barrier --
        if (t > 0) {
            uint32_t mb = smbase + SMB_MBAR + (uint32_t)((t & 1) * 16)
                        + (uint32_t)(kh * 8);
            if (t & 1) { mbar_wait_cluster(mb, ph1); ph1 ^= 1; }
            else       { mbar_wait_cluster(mb, ph0); ph0 ^= 1; }
        }

        {
            float acc[2][4][4];
            float accH[2][4];
            #pragma unroll
            for (int t2 = 0; t2 < 2; t2++) {
                #pragma unroll
                for (int kc = 0; kc < 4; kc++)
                    #pragma unroll
                    for (int q = 0; q < 4; q++) acc[t2][kc][q] = 0.f;
                #pragma unroll
                for (int q = 0; q < 4; q++) accH[t2][q] = 0.f;
            }

            #pragma unroll
            for (int ks = 0; ks < 8; ks++) {
                const int kk0 = kbase + ks * 16;
                const int kc  = ks & 3;
                const int blk = kk0 >> 5;
                uint32_t aoff = hinBase + (uint32_t)(blk * RANK_BLK
                               + a_row_l * HROW + ((kk0 & 16) + a_koff) * 2);
                uint32_t aHi[4], aLo[4];
                ldsm_x4(aHi, aoff);
                ldsm_x4(aLo, aoff + LO_OFF);
                uint32_t boff =
                    (uint32_t)((kk0 + b_krow) * WSTRIDE + wn * 16 + b_ncol) * 2;
                uint32_t bHi[4], bLo[4];
                ldsm_x4_t(bHi, sWhHi + boff);
                ldsm_x4_t(bLo, sWhLo + boff);
                #pragma unroll
                for (int t2 = 0; t2 < 2; t2++) {
                    mma_bf16(acc[t2][kc], aHi, bHi[t2 * 2], bHi[t2 * 2 + 1]);
                    mma_bf16(acc[t2][kc], aHi, bLo[t2 * 2], bLo[t2 * 2 + 1]);
                    mma_bf16(acc[t2][kc], aLo, bHi[t2 * 2], bHi[t2 * 2 + 1]);
                }
                if (wn == 0) {
                    uint32_t hoff = (uint32_t)((kk0 + b_krow) * WSTRIDE + 128) * 2;
                    uint32_t hH[2], hL[2];
                    ldsm_x2_t(hH, sWhHi + hoff);
                    ldsm_x2_t(hL, sWhLo + hoff);
                    const int kc2 = ks & 1;
                    mma_bf16(accH[kc2], aHi, hH[0], hH[1]);
                    mma_bf16(accH[kc2], aHi, hL[0], hL[1]);
                    mma_bf16(accH[kc2], aLo, hH[0], hH[1]);
                }
            }
            int r0 = lane >> 2;
            int cb = wn * 16 + 2 * (lane & 3);
            #pragma unroll
            for (int t2 = 0; t2 < 2; t2++) {
                int col = cb + 8 * t2;
                float v0 = (acc[t2][0][0] + acc[t2][1][0]) + (acc[t2][2][0] + acc[t2][3][0]);
                float v1 = (acc[t2][0][1] + acc[t2][1][1]) + (acc[t2][2][1] + acc[t2][3][1]);
                float v2 = (acc[t2][0][2] + acc[t2][1][2]) + (acc[t2][2][2] + acc[t2][3][2]);
                float v3 = (acc[t2][0][3] + acc[t2][1][3]) + (acc[t2][2][3] + acc[t2][3][3]);
                *(float2*)&zw_s[r0 * ZSTRIDE + col] = make_float2(v0, v1);
                *(float2*)&zw_s[(r0 + 8) * ZSTRIDE + col] = make_float2(v2, v3);
            }
            if (wn == 0) {
                int colH = 128 + 2 * (lane & 3);
                float h0 = accH[0][0] + accH[1][0];
                float h1 = accH[0][1] + accH[1][1];
                float h2 = accH[0][2] + accH[1][2];
                float h3 = accH[0][3] + accH[1][3];
                *(float2*)&zw_s[r0 * ZSTRIDE + colH] = make_float2(h0, h1);
                *(float2*)&zw_s[(r0 + 8) * ZSTRIDE + colH] = make_float2(h2, h3);
            }
        }
        __syncthreads();

        if (t > 0) {
            if (tid < 64) {
                int b = tid >> 2, q = tid & 3;
                out[((size_t)(t - 1) * BATCH + b0 + b) * OUTC + (int)rank + 8 * q]
                    = z0_s[b * ZSTRIDE + 128 + q] + z1_s[b * ZSTRIDE + 128 + q] + bo_s[q];
            } else if (rank == 0 && tid < 80) {
                int b = tid - 64;
                out[((size_t)(t - 1) * BATCH + b0 + b) * OUTC + 32]
                    = z0_s[b * ZSTRIDE + 132] + z1_s[b * ZSTRIDE + 132] + bo_s[4];
            }
        }

        {
            float zi = z0_s[gb * ZSTRIDE + gj]      + z1_s[gb * ZSTRIDE + gj];
            float zf = z0_s[gb * ZSTRIDE + 32 + gj] + z1_s[gb * ZSTRIDE + 32 + gj];
            float zg = z0_s[gb * ZSTRIDE + 64 + gj] + z1_s[gb * ZSTRIDE + 64 + gj];
            float zo = z0_s[gb * ZSTRIDE + 96 + gj] + z1_s[gb * ZSTRIDE + 96 + gj];
            float c_old = c_s[gb * 32 + gj];
            if (ep) { zi = 0.f; zf = 0.f; zg = 0.f; zo = 0.f; c_old = 0.f; }
            float iz = zi + xi;
            float fz = zf + xf;
            float gz = zg + xg;
            float oz = zo + xo;
            float nc = fsig(fz) * c_old + fsig(iz) * ftanh(gz);
            float nh = fsig(oz) * ftanh(nc);
            c_s[gb * 32 + gj] = nc;
            __nv_bfloat16 hi = __float2bfloat16_rn(nh);
            __nv_bfloat16 lo = __float2bfloat16_rn(nh - __bfloat162float(hi));
            *(__nv_bfloat16*)(houtB + gb * HROW + gj * 2) = hi;
            *(__nv_bfloat16*)(houtB + LO_OFF + gb * HROW + gj * 2) = lo;
        }
        __syncthreads();

        // -- bulk copy my 2560 B block to each peer; complete its half-barrier --
        if (tid < 7) {
            asm volatile("fence.proxy.async.shared::cta;" ::: "memory");
            uint32_t src = smbase + (uint32_t)(SMB_HB + p_out * HBUF
                                               + (int)rank * RANK_BLK);
            uint32_t dst, mb;
            asm("mapa.shared::cluster.u32 %0, %1, %2;"
                : "=r"(dst) : "r"(src), "r"(cp_peer));
            uint32_t mbl = smbase + SMB_MBAR + (uint32_t)(((t + 1) & 1) * 16)
                         + my_half_off;
            asm("mapa.shared::cluster.u32 %0, %1, %2;"
                : "=r"(mb) : "r"(mbl), "r"(cp_peer));
            asm volatile(
                "cp.async.bulk.shared::cluster.shared::cta.mbarrier::complete_tx::bytes "
                "[%0], [%1], %2, [%3];"
                :: "r"(dst), "r"(src), "r"((uint32_t)RANK_BLK), "r"(mb) : "memory");
        }
    }

    // final: wait BOTH phase-0 half-barriers, then fp32 head for t = 511
    {
        mbar_wait_cluster(smbase + SMB_MBAR,     ph0);
        mbar_wait_cluster(smbase + SMB_MBAR + 8, ph0);
        do_head(smraw + SMB_HB + 1 * HBUF, Wo_s, bo_s, out,
                T_STEPS - 1, b0, (int)rank, wid, lane);
    }

    asm volatile("barrier.cluster.arrive.aligned;" ::: "memory");
    asm volatile("barrier.cluster.wait.aligned;"   ::: "memory");
}

// ---------------------------------------------------------------------------
extern "C" void kernel_launch(void* const* d_in, const int* in_sizes, int n_in,
                              void* d_out, int out_size) {
    const float* inputs  = (const float*)d_in[0];
    const int*   epi     = (const int*)  d_in[1];
    const float* carry_c = (const float*)d_in[2];
    const float* carry_h = (const float*)d_in[3];
    const float* Wx      = (const float*)d_in[4];
    const float* Wh      = (const float*)d_in[5];
    const float* bias    = (const float*)d_in[6];
    const float* Wa      = (const float*)d_in[7];
    const float* ba      = (const float*)d_in[8];
    const float* Wv      = (const float*)d_in[9];
    const float* bv      = (const float*)d_in[10];
    float* out = (float*)d_out;

    cudaFuncSetAttribute(xproj_mma_kernel,
                         cudaFuncAttributeMaxDynamicSharedMemorySize, X2_SMEM);
    cudaFuncSetAttribute(lstm_rec_kernel,
                         cudaFuncAttributeMaxDynamicSharedMemorySize, RSMEM_BYTES);

    split_kernel<<<2048, 256>>>(inputs, Wx);

    dim3 g1(FOURH / 128, M_ROWS / 128);   // (8, 1024)
    xproj_mma_kernel<<<g1, 256, X2_SMEM>>>(bias);

    lstm_rec_kernel<<<(BATCH / NB) * CLUSTER, RTHREADS, RSMEM_BYTES>>>(
        epi, carry_c, carry_h, Wh, Wa, ba, Wv, bv, out);
}